// round 1
// baseline (speedup 1.0000x reference)
#include <cuda_runtime.h>
#include <math.h>
#include <stdint.h>

#define BB 2
#define NN 2048
#define CC 1024
#define HH 16
#define DD 64
#define FF 4096
#define TT (BB*NN)          // 4096 tokens

// ---------------- scratch (device globals: allocation-guard-safe) ----------------
__device__ float g_xn [(size_t)TT*CC];
__device__ float g_q  [(size_t)TT*CC];
__device__ float g_k  [(size_t)TT*CC];
__device__ float g_v  [(size_t)TT*CC];
__device__ float g_S  [(size_t)BB*HH*NN*NN];   // 512 MB attention scores
__device__ float g_y  [(size_t)TT*CC];
__device__ float g_x1 [(size_t)TT*CC];
__device__ float g_xn2[(size_t)TT*CC];
__device__ float g_h  [(size_t)TT*FF];

// ---------------- reductions ----------------
__device__ __forceinline__ float blockReduceSum256(float v) {
    __shared__ float sm[8];
    #pragma unroll
    for (int o = 16; o > 0; o >>= 1) v += __shfl_xor_sync(0xffffffffu, v, o);
    __syncthreads();
    if ((threadIdx.x & 31) == 0) sm[threadIdx.x >> 5] = v;
    __syncthreads();
    float t = 0.f;
    #pragma unroll
    for (int i = 0; i < 8; i++) t += sm[i];
    return t;
}

__device__ __forceinline__ float blockReduceMax256(float v) {
    __shared__ float sm[8];
    #pragma unroll
    for (int o = 16; o > 0; o >>= 1) v = fmaxf(v, __shfl_xor_sync(0xffffffffu, v, o));
    __syncthreads();
    if ((threadIdx.x & 31) == 0) sm[threadIdx.x >> 5] = v;
    __syncthreads();
    float t = -INFINITY;
    #pragma unroll
    for (int i = 0; i < 8; i++) t = fmaxf(t, sm[i]);
    return t;
}

// ---------------- layernorm: one block per row (C=1024, 256 thr, float4) ----------------
__global__ __launch_bounds__(256) void layernorm_kernel(
    const float* __restrict__ x, const float* __restrict__ gamma,
    const float* __restrict__ beta, float* __restrict__ out)
{
    const size_t row = (size_t)blockIdx.x * CC;
    const int c = threadIdx.x * 4;
    float4 v = *(const float4*)(x + row + c);

    float s = v.x + v.y + v.z + v.w;
    s = blockReduceSum256(s);
    float mu = s * (1.0f / CC);

    float dx = v.x - mu, dy = v.y - mu, dz = v.z - mu, dw = v.w - mu;
    float ss = dx*dx + dy*dy + dz*dz + dw*dw;
    ss = blockReduceSum256(ss);
    float rstd = rsqrtf(ss * (1.0f / CC) + 1e-6f);

    float4 g = *(const float4*)(gamma + c);
    float4 b = *(const float4*)(beta + c);
    float4 o;
    o.x = dx * rstd * g.x + b.x;
    o.y = dy * rstd * g.y + b.y;
    o.z = dz * rstd * g.z + b.z;
    o.w = dw * rstd * g.w + b.w;
    *(float4*)(out + row + c) = o;
}

// ---------------- SGEMM 128x128x8, 256 thr, 8x8 microtile ----------------
// C = epilogue(scale*(A@B)); epilogue: +bias, gelu(exact), +res   (in that order)
__global__ __launch_bounds__(256) void sgemm_kernel(
    const float* __restrict__ A, const float* __restrict__ Bm,
    const float* __restrict__ bias, const float* __restrict__ res,
    float* __restrict__ C, int M, int N, int K, float scale, int do_gelu)
{
    __shared__ float As[8][128];
    __shared__ float Bs[8][128];

    const int tid = threadIdx.x;
    const int bx = blockIdx.x, by = blockIdx.y;
    const int tx = tid & 15, ty = tid >> 4;

    const int a_row = tid >> 1;          // 0..127
    const int a_col = (tid & 1) * 4;     // 0 or 4
    const int b_row = tid >> 5;          // 0..7
    const int b_col = (tid & 31) * 4;    // 0..124

    const float* Aptr = A + (size_t)(by * 128 + a_row) * K + a_col;
    const float* Bptr = Bm + (size_t)b_row * N + bx * 128 + b_col;

    float acc[8][8];
    #pragma unroll
    for (int i = 0; i < 8; i++)
        #pragma unroll
        for (int j = 0; j < 8; j++) acc[i][j] = 0.f;

    for (int k0 = 0; k0 < K; k0 += 8) {
        float4 av = *(const float4*)(Aptr + k0);
        As[a_col + 0][a_row] = av.x;
        As[a_col + 1][a_row] = av.y;
        As[a_col + 2][a_row] = av.z;
        As[a_col + 3][a_row] = av.w;
        *(float4*)&Bs[b_row][b_col] = *(const float4*)(Bptr + (size_t)k0 * N);
        __syncthreads();

        #pragma unroll
        for (int kk = 0; kk < 8; kk++) {
            float ra[8], rb[8];
            #pragma unroll
            for (int i = 0; i < 8; i++) ra[i] = As[kk][ty * 8 + i];
            #pragma unroll
            for (int j = 0; j < 8; j++) rb[j] = Bs[kk][tx * 8 + j];
            #pragma unroll
            for (int i = 0; i < 8; i++)
                #pragma unroll
                for (int j = 0; j < 8; j++)
                    acc[i][j] = fmaf(ra[i], rb[j], acc[i][j]);
        }
        __syncthreads();
    }

    const int crow0 = by * 128 + ty * 8;
    const int ccol0 = bx * 128 + tx * 8;
    #pragma unroll
    for (int i = 0; i < 8; i++) {
        const size_t rowoff = (size_t)(crow0 + i) * N;
        #pragma unroll
        for (int j = 0; j < 8; j++) {
            const int ccol = ccol0 + j;
            float v = acc[i][j] * scale;
            if (bias) v += bias[ccol];
            if (do_gelu) v = 0.5f * v * (1.0f + erff(v * 0.70710678118654752f));
            if (res) v += res[rowoff + ccol];
            C[rowoff + ccol] = v;
        }
    }
}

// ---------------- attention scores: S[bh] = Q[bh] @ K[bh]^T (q pre-scaled) ----------------
// grid: (N/64, N/64, B*H); block 256; Q,K laid out (B,N,H,D)
__global__ __launch_bounds__(256) void attn_scores_kernel(
    const float* __restrict__ q, const float* __restrict__ k, float* __restrict__ S)
{
    __shared__ float Qs[DD][65];   // [d][n]
    __shared__ float Ks[DD][65];   // [d][m]

    const int bh = blockIdx.z;
    const int b = bh >> 4, h = bh & 15;
    const int m0 = blockIdx.x * 64, n0 = blockIdx.y * 64;
    const int tid = threadIdx.x;

    const float* qbase = q + (size_t)b * NN * CC + h * DD;
    const float* kbase = k + (size_t)b * NN * CC + h * DD;

    #pragma unroll
    for (int i = 0; i < 4; i++) {
        int lin = tid + i * 256;       // 0..1023
        int r = lin >> 4;              // 0..63
        int c = (lin & 15) * 4;        // 0..60
        float4 v = *(const float4*)(qbase + (size_t)(n0 + r) * CC + c);
        Qs[c + 0][r] = v.x; Qs[c + 1][r] = v.y; Qs[c + 2][r] = v.z; Qs[c + 3][r] = v.w;
        float4 w = *(const float4*)(kbase + (size_t)(m0 + r) * CC + c);
        Ks[c + 0][r] = w.x; Ks[c + 1][r] = w.y; Ks[c + 2][r] = w.z; Ks[c + 3][r] = w.w;
    }
    __syncthreads();

    const int tx = tid & 15, ty = tid >> 4;
    float acc[4][4];
    #pragma unroll
    for (int i = 0; i < 4; i++)
        #pragma unroll
        for (int j = 0; j < 4; j++) acc[i][j] = 0.f;

    #pragma unroll 8
    for (int d = 0; d < DD; d++) {
        float rq[4], rk[4];
        #pragma unroll
        for (int i = 0; i < 4; i++) rq[i] = Qs[d][ty * 4 + i];
        #pragma unroll
        for (int j = 0; j < 4; j++) rk[j] = Ks[d][tx * 4 + j];
        #pragma unroll
        for (int i = 0; i < 4; i++)
            #pragma unroll
            for (int j = 0; j < 4; j++)
                acc[i][j] = fmaf(rq[i], rk[j], acc[i][j]);
    }

    float* Sp = S + (size_t)bh * NN * NN;
    #pragma unroll
    for (int i = 0; i < 4; i++) {
        const size_t ro = (size_t)(n0 + ty * 4 + i) * NN + m0;
        #pragma unroll
        for (int j = 0; j < 4; j++)
            Sp[ro + tx * 4 + j] = acc[i][j];
    }
}

// ---------------- softmax over last dim of S, in place. grid (N, B*H), 256 thr ----------------
__global__ __launch_bounds__(256) void softmax_kernel(float* __restrict__ S)
{
    float* row = S + ((size_t)blockIdx.y * NN + blockIdx.x) * NN;
    const int tid = threadIdx.x;

    float vals[8];
    float m = -INFINITY;
    #pragma unroll
    for (int i = 0; i < 8; i++) { vals[i] = row[tid + i * 256]; m = fmaxf(m, vals[i]); }
    m = blockReduceMax256(m);

    float s = 0.f;
    #pragma unroll
    for (int i = 0; i < 8; i++) { vals[i] = __expf(vals[i] - m); s += vals[i]; }
    s = blockReduceSum256(s);
    const float inv = 1.0f / s;

    #pragma unroll
    for (int i = 0; i < 8; i++) row[tid + i * 256] = vals[i] * inv;
}

// ---------------- attn output: O[bh] = S[bh] @ V[bh], written to (B,N,C) layout ----------------
// grid: (N/64, B*H); block 256; 64 rows x 64 cols (full D), K-chunks of 32
__global__ __launch_bounds__(256) void attn_out_kernel(
    const float* __restrict__ S, const float* __restrict__ v, float* __restrict__ y)
{
    __shared__ float Ss[32][65];   // [k][n]
    __shared__ float Vs[32][64];   // [k][d]

    const int bh = blockIdx.y;
    const int b = bh >> 4, h = bh & 15;
    const int n0 = blockIdx.x * 64;
    const int tid = threadIdx.x;
    const int tx = tid & 15, ty = tid >> 4;

    const float* Sp = S + (size_t)bh * NN * NN;
    const float* vbase = v + (size_t)b * NN * CC + h * DD;

    float acc[4][4];
    #pragma unroll
    for (int i = 0; i < 4; i++)
        #pragma unroll
        for (int j = 0; j < 4; j++) acc[i][j] = 0.f;

    for (int k0 = 0; k0 < NN; k0 += 32) {
        #pragma unroll
        for (int i = 0; i < 2; i++) {
            int lin = tid + i * 256;   // 0..511
            int r = lin >> 3;          // 0..63
            int c = (lin & 7) * 4;     // 0..28
            float4 sv = *(const float4*)(Sp + (size_t)(n0 + r) * NN + k0 + c);
            Ss[c + 0][r] = sv.x; Ss[c + 1][r] = sv.y; Ss[c + 2][r] = sv.z; Ss[c + 3][r] = sv.w;
        }
        #pragma unroll
        for (int i = 0; i < 2; i++) {
            int lin = tid + i * 256;
            int r = lin >> 4;          // 0..31
            int c = (lin & 15) * 4;    // 0..60
            *(float4*)&Vs[r][c] = *(const float4*)(vbase + (size_t)(k0 + r) * CC + c);
        }
        __syncthreads();

        #pragma unroll
        for (int kk = 0; kk < 32; kk++) {
            float rs[4], rv[4];
            #pragma unroll
            for (int i = 0; i < 4; i++) rs[i] = Ss[kk][ty * 4 + i];
            #pragma unroll
            for (int j = 0; j < 4; j++) rv[j] = Vs[kk][tx * 4 + j];
            #pragma unroll
            for (int i = 0; i < 4; i++)
                #pragma unroll
                for (int j = 0; j < 4; j++)
                    acc[i][j] = fmaf(rs[i], rv[j], acc[i][j]);
        }
        __syncthreads();
    }

    float* yp = y + (size_t)b * NN * CC + h * DD;
    #pragma unroll
    for (int i = 0; i < 4; i++) {
        const size_t ro = (size_t)(n0 + ty * 4 + i) * CC;
        #pragma unroll
        for (int j = 0; j < 4; j++)
            yp[ro + tx * 4 + j] = acc[i][j];
    }
}

// ---------------- launch ----------------
extern "C" void kernel_launch(void* const* d_in, const int* in_sizes, int n_in,
                              void* d_out, int out_size)
{
    const float* x      = (const float*)d_in[0];
    const float* Wq     = (const float*)d_in[1];
    const float* Wk     = (const float*)d_in[2];
    const float* Wv     = (const float*)d_in[3];
    const float* Wp     = (const float*)d_in[4];
    const float* bp     = (const float*)d_in[5];
    const float* W1     = (const float*)d_in[6];
    const float* b1     = (const float*)d_in[7];
    const float* W2     = (const float*)d_in[8];
    const float* b2     = (const float*)d_in[9];
    const float* gamma1 = (const float*)d_in[10];
    const float* beta1  = (const float*)d_in[11];
    const float* gamma2 = (const float*)d_in[12];
    const float* beta2  = (const float*)d_in[13];
    float* out = (float*)d_out;

    float *xn, *q, *k, *v, *S, *y, *x1, *xn2, *hb;
    cudaGetSymbolAddress((void**)&xn,  g_xn);
    cudaGetSymbolAddress((void**)&q,   g_q);
    cudaGetSymbolAddress((void**)&k,   g_k);
    cudaGetSymbolAddress((void**)&v,   g_v);
    cudaGetSymbolAddress((void**)&S,   g_S);
    cudaGetSymbolAddress((void**)&y,   g_y);
    cudaGetSymbolAddress((void**)&x1,  g_x1);
    cudaGetSymbolAddress((void**)&xn2, g_xn2);
    cudaGetSymbolAddress((void**)&hb,  g_h);

    const float qscale = 0.125f;   // D^-0.5, D=64

    // 1) LN1
    layernorm_kernel<<<TT, 256>>>(x, gamma1, beta1, xn);

    // 2) QKV projections
    {
        dim3 g(CC / 128, TT / 128);
        sgemm_kernel<<<g, 256>>>(xn, Wq, nullptr, nullptr, q, TT, CC, CC, qscale, 0);
        sgemm_kernel<<<g, 256>>>(xn, Wk, nullptr, nullptr, k, TT, CC, CC, 1.0f, 0);
        sgemm_kernel<<<g, 256>>>(xn, Wv, nullptr, nullptr, v, TT, CC, CC, 1.0f, 0);
    }

    // 3) attention
    {
        dim3 g(NN / 64, NN / 64, BB * HH);
        attn_scores_kernel<<<g, 256>>>(q, k, S);
    }
    {
        dim3 g(NN, BB * HH);
        softmax_kernel<<<g, 256>>>(S);
    }
    {
        dim3 g(NN / 64, BB * HH);
        attn_out_kernel<<<g, 256>>>(S, v, y);
    }

    // 4) output projection + residual: x1 = x + y@Wp + bp
    {
        dim3 g(CC / 128, TT / 128);
        sgemm_kernel<<<g, 256>>>(y, Wp, bp, x, x1, TT, CC, CC, 1.0f, 0);
    }

    // 5) LN2
    layernorm_kernel<<<TT, 256>>>(x1, gamma2, beta2, xn2);

    // 6) MLP
    {
        dim3 g(FF / 128, TT / 128);
        sgemm_kernel<<<g, 256>>>(xn2, W1, b1, nullptr, hb, TT, FF, CC, 1.0f, 1);
    }
    {
        dim3 g(CC / 128, TT / 128);
        sgemm_kernel<<<g, 256>>>(hb, W2, b2, x1, out, TT, CC, FF, 1.0f, 0);
    }
}

// round 2
// speedup vs baseline: 5.0806x; 5.0806x over previous
#include <cuda_runtime.h>
#include <math.h>
#include <stdint.h>

#define BB 2
#define NN 2048
#define CC 1024
#define HH 16
#define DD 64
#define FF 4096
#define TT (BB*NN)          // 4096 tokens

// ---------------- scratch (device globals) ----------------
__device__ float g_xn [(size_t)TT*CC];
__device__ float g_q  [(size_t)TT*CC];
__device__ float g_k  [(size_t)TT*CC];
__device__ float g_v  [(size_t)TT*CC];
__device__ float g_S  [(size_t)BB*HH*NN*NN];   // 512 MB attention scores
__device__ float g_y  [(size_t)TT*CC];
__device__ float g_x1 [(size_t)TT*CC];
__device__ float g_xn2[(size_t)TT*CC];
__device__ float g_h  [(size_t)TT*FF];
// tf32-rounded weights
__device__ float g_wq [(size_t)CC*CC];
__device__ float g_wk [(size_t)CC*CC];
__device__ float g_wv [(size_t)CC*CC];
__device__ float g_wp [(size_t)CC*CC];
__device__ float g_w1 [(size_t)CC*FF];
__device__ float g_w2 [(size_t)FF*CC];

// ---------------- helpers ----------------
__device__ __forceinline__ float tf32r(float x) {
    uint32_t u;
    asm("cvt.rna.tf32.f32 %0, %1;" : "=r"(u) : "f"(x));
    return __uint_as_float(u);
}

__device__ __forceinline__ void mma_tf32(float4& d,
    uint32_t a0, uint32_t a1, uint32_t a2, uint32_t a3, uint32_t b0, uint32_t b1)
{
    asm volatile(
        "mma.sync.aligned.m16n8k8.row.col.f32.tf32.tf32.f32 "
        "{%0,%1,%2,%3}, {%4,%5,%6,%7}, {%8,%9}, {%0,%1,%2,%3};\n"
        : "+f"(d.x), "+f"(d.y), "+f"(d.z), "+f"(d.w)
        : "r"(a0), "r"(a1), "r"(a2), "r"(a3), "r"(b0), "r"(b1));
}

__device__ __forceinline__ void cp16(void* smem_dst, const void* gsrc) {
    uint32_t d = (uint32_t)__cvta_generic_to_shared(smem_dst);
    asm volatile("cp.async.cg.shared.global [%0], [%1], 16;\n" :: "r"(d), "l"(gsrc));
}
__device__ __forceinline__ void cp_commit() { asm volatile("cp.async.commit_group;\n"); }
__device__ __forceinline__ void cp_wait0() { asm volatile("cp.async.wait_group 0;\n"); }
__device__ __forceinline__ void cp_wait1() { asm volatile("cp.async.wait_group 1;\n"); }

__device__ __forceinline__ float blockReduceSum256(float v) {
    __shared__ float sm[8];
    #pragma unroll
    for (int o = 16; o > 0; o >>= 1) v += __shfl_xor_sync(0xffffffffu, v, o);
    __syncthreads();
    if ((threadIdx.x & 31) == 0) sm[threadIdx.x >> 5] = v;
    __syncthreads();
    float t = 0.f;
    #pragma unroll
    for (int i = 0; i < 8; i++) t += sm[i];
    return t;
}

__device__ __forceinline__ float blockReduceMax256(float v) {
    __shared__ float sm[8];
    #pragma unroll
    for (int o = 16; o > 0; o >>= 1) v = fmaxf(v, __shfl_xor_sync(0xffffffffu, v, o));
    __syncthreads();
    if ((threadIdx.x & 31) == 0) sm[threadIdx.x >> 5] = v;
    __syncthreads();
    float t = -INFINITY;
    #pragma unroll
    for (int i = 0; i < 8; i++) t = fmaxf(t, sm[i]);
    return t;
}

// ---------------- weight rounding (fp32 -> tf32-exact fp32) ----------------
__global__ __launch_bounds__(256) void round_tf32_kernel(
    const float* __restrict__ in, float* __restrict__ out, int n4)
{
    int i = blockIdx.x * 256 + threadIdx.x;
    if (i < n4) {
        float4 v = ((const float4*)in)[i];
        v.x = tf32r(v.x); v.y = tf32r(v.y); v.z = tf32r(v.z); v.w = tf32r(v.w);
        ((float4*)out)[i] = v;
    }
}

// ---------------- layernorm (output tf32-rounded: feeds GEMMs) ----------------
__global__ __launch_bounds__(256) void layernorm_kernel(
    const float* __restrict__ x, const float* __restrict__ gamma,
    const float* __restrict__ beta, float* __restrict__ out)
{
    const size_t row = (size_t)blockIdx.x * CC;
    const int c = threadIdx.x * 4;
    float4 v = *(const float4*)(x + row + c);

    float s = v.x + v.y + v.z + v.w;
    s = blockReduceSum256(s);
    float mu = s * (1.0f / CC);

    float dx = v.x - mu, dy = v.y - mu, dz = v.z - mu, dw = v.w - mu;
    float ss = dx*dx + dy*dy + dz*dz + dw*dw;
    ss = blockReduceSum256(ss);
    float rstd = rsqrtf(ss * (1.0f / CC) + 1e-6f);

    float4 g = *(const float4*)(gamma + c);
    float4 b = *(const float4*)(beta + c);
    float4 o;
    o.x = tf32r(dx * rstd * g.x + b.x);
    o.y = tf32r(dy * rstd * g.y + b.y);
    o.z = tf32r(dz * rstd * g.z + b.z);
    o.w = tf32r(dw * rstd * g.w + b.w);
    *(float4*)(out + row + c) = o;
}

// ---------------- TF32 tensor-core GEMM 128x128x16, cp.async double-buffered --------
// C = epi(scale*(A@B)) ; epi order: +bias, gelu, +res, [round to tf32]
__global__ __launch_bounds__(256) void tf32_gemm_kernel(
    const float* __restrict__ A, const float* __restrict__ Bm,
    const float* __restrict__ bias, const float* __restrict__ res,
    float* __restrict__ C, int N, int K, float scale, int do_gelu, int do_round)
{
    __shared__ float As[2][128][20];   // [buf][m][k+4]
    __shared__ float Bs[2][16][136];   // [buf][k][n+8]

    const int tid = threadIdx.x;
    const int lane = tid & 31;
    const int wid = tid >> 5;
    const int bx = blockIdx.x, by = blockIdx.y;
    const int m0w = (wid >> 2) * 64;
    const int n0w = (wid & 3) * 32;

    float4 acc[4][4];
    #pragma unroll
    for (int i = 0; i < 4; i++)
        #pragma unroll
        for (int j = 0; j < 4; j++) acc[i][j] = make_float4(0.f, 0.f, 0.f, 0.f);

    const int a_row = tid >> 1;              // 0..127  (2 chunks per thread)
    const int b_row = tid >> 5;              // 0..7    (2 chunks per thread)
    const int KT = K >> 4;

    // tile loaders
    auto loadTile = [&](int kt, int buf) {
        const int k0 = kt << 4;
        #pragma unroll
        for (int i = 0; i < 2; i++) {
            int c = tid + i * 256;           // A: 512 chunks
            int r = c >> 2, c4 = (c & 3) * 4;
            cp16(&As[buf][r][c4], A + (size_t)(by * 128 + r) * K + k0 + c4);
        }
        #pragma unroll
        for (int i = 0; i < 2; i++) {
            int c = tid + i * 256;           // B: 512 chunks
            int r = c >> 5, c4 = (c & 31) * 4;
            cp16(&Bs[buf][r][c4], Bm + (size_t)(k0 + r) * N + bx * 128 + c4);
        }
        cp_commit();
    };

    loadTile(0, 0);
    int buf = 0;
    for (int kt = 0; kt < KT; kt++) {
        if (kt + 1 < KT) { loadTile(kt + 1, buf ^ 1); cp_wait1(); }
        else cp_wait0();
        __syncthreads();

        #pragma unroll
        for (int kk = 0; kk < 16; kk += 8) {
            uint32_t af[4][4];
            #pragma unroll
            for (int im = 0; im < 4; im++) {
                const float* p = &As[buf][m0w + im * 16 + (lane >> 2)][kk + (lane & 3)];
                af[im][0] = __float_as_uint(p[0]);
                af[im][1] = __float_as_uint(p[8 * 20]);
                af[im][2] = __float_as_uint(p[4]);
                af[im][3] = __float_as_uint(p[8 * 20 + 4]);
            }
            uint32_t bf[4][2];
            #pragma unroll
            for (int in = 0; in < 4; in++) {
                const float* p = &Bs[buf][kk + (lane & 3)][n0w + in * 8 + (lane >> 2)];
                bf[in][0] = __float_as_uint(p[0]);
                bf[in][1] = __float_as_uint(p[4 * 136]);
            }
            #pragma unroll
            for (int im = 0; im < 4; im++)
                #pragma unroll
                for (int in = 0; in < 4; in++)
                    mma_tf32(acc[im][in], af[im][0], af[im][1], af[im][2], af[im][3],
                             bf[in][0], bf[in][1]);
        }
        __syncthreads();
        buf ^= 1;
    }

    // epilogue
    #pragma unroll
    for (int im = 0; im < 4; im++) {
        #pragma unroll
        for (int in = 0; in < 4; in++) {
            int row = by * 128 + m0w + im * 16 + (lane >> 2);
            int col = bx * 128 + n0w + in * 8 + (lane & 3) * 2;
            #pragma unroll
            for (int half = 0; half < 2; half++) {
                int r = row + half * 8;
                float v0 = (half ? acc[im][in].z : acc[im][in].x) * scale;
                float v1 = (half ? acc[im][in].w : acc[im][in].y) * scale;
                if (bias) { v0 += bias[col]; v1 += bias[col + 1]; }
                if (do_gelu) {
                    v0 = 0.5f * v0 * (1.0f + erff(v0 * 0.70710678118654752f));
                    v1 = 0.5f * v1 * (1.0f + erff(v1 * 0.70710678118654752f));
                }
                if (res) {
                    v0 += res[(size_t)r * N + col];
                    v1 += res[(size_t)r * N + col + 1];
                }
                if (do_round) { v0 = tf32r(v0); v1 = tf32r(v1); }
                *(float2*)(C + (size_t)r * N + col) = make_float2(v0, v1);
            }
        }
    }
}

// ---------------- attention scores (tf32 MMA): S[bh][n][m] = Q[n,:]·K[m,:] ----------
// grid (NN/128 m, NN/128 n, B*H), 256 thr
__global__ __launch_bounds__(256) void attn_scores_tf32(
    const float* __restrict__ q, const float* __restrict__ k, float* __restrict__ S)
{
    __shared__ float Qs[128][36];   // [n][d_chunk+4]
    __shared__ float Ks[128][36];   // [m][d_chunk+4]

    const int bh = blockIdx.z;
    const int b = bh >> 4, h = bh & 15;
    const int m0 = blockIdx.x * 128, n0 = blockIdx.y * 128;
    const int tid = threadIdx.x;
    const int lane = tid & 31;
    const int wid = tid >> 5;
    const int m0w = (wid >> 2) * 64;   // row (n) offset within tile
    const int n0w = (wid & 3) * 32;    // col (m) offset within tile

    const float* qbase = q + (size_t)b * NN * CC + h * DD;
    const float* kbase = k + (size_t)b * NN * CC + h * DD;

    float4 acc[4][4];
    #pragma unroll
    for (int i = 0; i < 4; i++)
        #pragma unroll
        for (int j = 0; j < 4; j++) acc[i][j] = make_float4(0.f, 0.f, 0.f, 0.f);

    for (int dc = 0; dc < DD; dc += 32) {
        #pragma unroll
        for (int i = 0; i < 4; i++) {
            int c = tid + i * 256;       // 0..1023
            int r = c >> 3, c4 = (c & 7) * 4;
            cp16(&Qs[r][c4], qbase + (size_t)(n0 + r) * CC + dc + c4);
            cp16(&Ks[r][c4], kbase + (size_t)(m0 + r) * CC + dc + c4);
        }
        cp_commit();
        cp_wait0();
        __syncthreads();

        #pragma unroll
        for (int kk = 0; kk < 32; kk += 8) {
            uint32_t af[4][4];
            #pragma unroll
            for (int im = 0; im < 4; im++) {
                const float* p = &Qs[m0w + im * 16 + (lane >> 2)][kk + (lane & 3)];
                af[im][0] = __float_as_uint(p[0]);
                af[im][1] = __float_as_uint(p[8 * 36]);
                af[im][2] = __float_as_uint(p[4]);
                af[im][3] = __float_as_uint(p[8 * 36 + 4]);
            }
            uint32_t bf[4][2];
            #pragma unroll
            for (int in = 0; in < 4; in++) {
                const float* p = &Ks[n0w + in * 8 + (lane >> 2)][kk + (lane & 3)];
                bf[in][0] = __float_as_uint(p[0]);
                bf[in][1] = __float_as_uint(p[4]);
            }
            #pragma unroll
            for (int im = 0; im < 4; im++)
                #pragma unroll
                for (int in = 0; in < 4; in++)
                    mma_tf32(acc[im][in], af[im][0], af[im][1], af[im][2], af[im][3],
                             bf[in][0], bf[in][1]);
        }
        __syncthreads();
    }

    float* Sp = S + (size_t)bh * NN * NN;
    #pragma unroll
    for (int im = 0; im < 4; im++) {
        #pragma unroll
        for (int in = 0; in < 4; in++) {
            int row = n0 + m0w + im * 16 + (lane >> 2);
            int col = m0 + n0w + in * 8 + (lane & 3) * 2;
            *(float2*)(Sp + (size_t)row * NN + col) = make_float2(acc[im][in].x, acc[im][in].y);
            *(float2*)(Sp + (size_t)(row + 8) * NN + col) = make_float2(acc[im][in].z, acc[im][in].w);
        }
    }
}

// ---------------- softmax (in place, output tf32-rounded) ----------------
__global__ __launch_bounds__(256) void softmax_kernel(float* __restrict__ S)
{
    float* row = S + ((size_t)blockIdx.y * NN + blockIdx.x) * NN;
    const int tid = threadIdx.x;

    float vals[8];
    float m = -INFINITY;
    #pragma unroll
    for (int i = 0; i < 8; i++) { vals[i] = row[tid + i * 256]; m = fmaxf(m, vals[i]); }
    m = blockReduceMax256(m);

    float s = 0.f;
    #pragma unroll
    for (int i = 0; i < 8; i++) { vals[i] = __expf(vals[i] - m); s += vals[i]; }
    s = blockReduceSum256(s);
    const float inv = 1.0f / s;

    #pragma unroll
    for (int i = 0; i < 8; i++) row[tid + i * 256] = tf32r(vals[i] * inv);
}

// ---------------- attn out (tf32 MMA): y[t, h*64+d] = sum_m S[n,m] V[m,d] ----------
// grid (NN/128, B*H), 256 thr; output tf32-rounded (feeds proj GEMM)
__global__ __launch_bounds__(256) void attn_out_tf32(
    const float* __restrict__ S, const float* __restrict__ v, float* __restrict__ y)
{
    __shared__ float Ss[2][128][20];   // [buf][n][m_chunk+4]
    __shared__ float Vs[2][16][72];    // [buf][m][d+8]

    const int bh = blockIdx.y;
    const int b = bh >> 4, h = bh & 15;
    const int n0 = blockIdx.x * 128;
    const int tid = threadIdx.x;
    const int lane = tid & 31;
    const int wid = tid >> 5;
    const int m0w = (wid >> 1) * 32;   // row (n) offset
    const int n0w = (wid & 1) * 32;    // col (d) offset

    const float* Sp = S + (size_t)bh * NN * NN;
    const float* vbase = v + (size_t)b * NN * CC + h * DD;

    float4 acc[2][4];
    #pragma unroll
    for (int i = 0; i < 2; i++)
        #pragma unroll
        for (int j = 0; j < 4; j++) acc[i][j] = make_float4(0.f, 0.f, 0.f, 0.f);

    auto loadTile = [&](int kt, int buf) {
        const int k0 = kt << 4;
        #pragma unroll
        for (int i = 0; i < 2; i++) {
            int c = tid + i * 256;           // S: 512 chunks
            int r = c >> 2, c4 = (c & 3) * 4;
            cp16(&Ss[buf][r][c4], Sp + (size_t)(n0 + r) * NN + k0 + c4);
        }
        {
            int r = tid >> 4, c4 = (tid & 15) * 4;   // V: 256 chunks
            cp16(&Vs[buf][r][c4], vbase + (size_t)(k0 + r) * CC + c4);
        }
        cp_commit();
    };

    loadTile(0, 0);
    int buf = 0;
    const int KT = NN >> 4;   // 128
    for (int kt = 0; kt < KT; kt++) {
        if (kt + 1 < KT) { loadTile(kt + 1, buf ^ 1); cp_wait1(); }
        else cp_wait0();
        __syncthreads();

        #pragma unroll
        for (int kk = 0; kk < 16; kk += 8) {
            uint32_t af[2][4];
            #pragma unroll
            for (int im = 0; im < 2; im++) {
                const float* p = &Ss[buf][m0w + im * 16 + (lane >> 2)][kk + (lane & 3)];
                af[im][0] = __float_as_uint(p[0]);
                af[im][1] = __float_as_uint(p[8 * 20]);
                af[im][2] = __float_as_uint(p[4]);
                af[im][3] = __float_as_uint(p[8 * 20 + 4]);
            }
            uint32_t bf[4][2];
            #pragma unroll
            for (int in = 0; in < 4; in++) {
                const float* p = &Vs[buf][kk + (lane & 3)][n0w + in * 8 + (lane >> 2)];
                bf[in][0] = __float_as_uint(p[0]);
                bf[in][1] = __float_as_uint(p[4 * 72]);
            }
            #pragma unroll
            for (int im = 0; im < 2; im++)
                #pragma unroll
                for (int in = 0; in < 4; in++)
                    mma_tf32(acc[im][in], af[im][0], af[im][1], af[im][2], af[im][3],
                             bf[in][0], bf[in][1]);
        }
        __syncthreads();
        buf ^= 1;
    }

    #pragma unroll
    for (int im = 0; im < 2; im++) {
        #pragma unroll
        for (int in = 0; in < 4; in++) {
            int n = n0 + m0w + im * 16 + (lane >> 2);
            int col = h * DD + n0w + in * 8 + (lane & 3) * 2;
            size_t t0 = ((size_t)b * NN + n) * CC + col;
            size_t t1 = ((size_t)b * NN + n + 8) * CC + col;
            *(float2*)(y + t0) = make_float2(tf32r(acc[im][in].x), tf32r(acc[im][in].y));
            *(float2*)(y + t1) = make_float2(tf32r(acc[im][in].z), tf32r(acc[im][in].w));
        }
    }
}

// ---------------- launch ----------------
extern "C" void kernel_launch(void* const* d_in, const int* in_sizes, int n_in,
                              void* d_out, int out_size)
{
    const float* x      = (const float*)d_in[0];
    const float* Wq     = (const float*)d_in[1];
    const float* Wk     = (const float*)d_in[2];
    const float* Wv     = (const float*)d_in[3];
    const float* Wp     = (const float*)d_in[4];
    const float* bp     = (const float*)d_in[5];
    const float* W1     = (const float*)d_in[6];
    const float* b1     = (const float*)d_in[7];
    const float* W2     = (const float*)d_in[8];
    const float* b2     = (const float*)d_in[9];
    const float* gamma1 = (const float*)d_in[10];
    const float* beta1  = (const float*)d_in[11];
    const float* gamma2 = (const float*)d_in[12];
    const float* beta2  = (const float*)d_in[13];
    float* out = (float*)d_out;

    float *xn, *q, *k, *v, *S, *y, *x1, *xn2, *hb;
    float *wq, *wk, *wv, *wp, *w1, *w2;
    cudaGetSymbolAddress((void**)&xn,  g_xn);
    cudaGetSymbolAddress((void**)&q,   g_q);
    cudaGetSymbolAddress((void**)&k,   g_k);
    cudaGetSymbolAddress((void**)&v,   g_v);
    cudaGetSymbolAddress((void**)&S,   g_S);
    cudaGetSymbolAddress((void**)&y,   g_y);
    cudaGetSymbolAddress((void**)&x1,  g_x1);
    cudaGetSymbolAddress((void**)&xn2, g_xn2);
    cudaGetSymbolAddress((void**)&hb,  g_h);
    cudaGetSymbolAddress((void**)&wq,  g_wq);
    cudaGetSymbolAddress((void**)&wk,  g_wk);
    cudaGetSymbolAddress((void**)&wv,  g_wv);
    cudaGetSymbolAddress((void**)&wp,  g_wp);
    cudaGetSymbolAddress((void**)&w1,  g_w1);
    cudaGetSymbolAddress((void**)&w2,  g_w2);

    const float qscale = 0.125f;   // D^-0.5, D=64

    // 0) round weights to tf32 grid
    {
        int n4a = CC * CC / 4, n4b = CC * FF / 4;
        round_tf32_kernel<<<(n4a + 255) / 256, 256>>>(Wq, wq, n4a);
        round_tf32_kernel<<<(n4a + 255) / 256, 256>>>(Wk, wk, n4a);
        round_tf32_kernel<<<(n4a + 255) / 256, 256>>>(Wv, wv, n4a);
        round_tf32_kernel<<<(n4a + 255) / 256, 256>>>(Wp, wp, n4a);
        round_tf32_kernel<<<(n4b + 255) / 256, 256>>>(W1, w1, n4b);
        round_tf32_kernel<<<(n4b + 255) / 256, 256>>>(W2, w2, n4b);
    }

    // 1) LN1 (tf32-rounded output)
    layernorm_kernel<<<TT, 256>>>(x, gamma1, beta1, xn);

    // 2) QKV projections (tf32 outputs)
    {
        dim3 g(CC / 128, TT / 128);
        tf32_gemm_kernel<<<g, 256>>>(xn, wq, nullptr, nullptr, q, CC, CC, qscale, 0, 1);
        tf32_gemm_kernel<<<g, 256>>>(xn, wk, nullptr, nullptr, k, CC, CC, 1.0f, 0, 1);
        tf32_gemm_kernel<<<g, 256>>>(xn, wv, nullptr, nullptr, v, CC, CC, 1.0f, 0, 1);
    }

    // 3) attention
    {
        dim3 g(NN / 128, NN / 128, BB * HH);
        attn_scores_tf32<<<g, 256>>>(q, k, S);
    }
    {
        dim3 g(NN, BB * HH);
        softmax_kernel<<<g, 256>>>(S);
    }
    {
        dim3 g(NN / 128, BB * HH);
        attn_out_tf32<<<g, 256>>>(S, v, y);
    }

    // 4) output projection + residual: x1 = x + y@Wp + bp   (fp32 out)
    {
        dim3 g(CC / 128, TT / 128);
        tf32_gemm_kernel<<<g, 256>>>(y, wp, bp, x, x1, CC, CC, 1.0f, 0, 0);
    }

    // 5) LN2 (tf32 output)
    layernorm_kernel<<<TT, 256>>>(x1, gamma2, beta2, xn2);

    // 6) MLP
    {
        dim3 g(FF / 128, TT / 128);
        tf32_gemm_kernel<<<g, 256>>>(xn2, w1, b1, nullptr, hb, FF, CC, 1.0f, 1, 1);
    }
    {
        dim3 g(CC / 128, TT / 128);
        tf32_gemm_kernel<<<g, 256>>>(hb, w2, b2, x1, out, CC, FF, 1.0f, 0, 0);
    }
}

// round 3
// speedup vs baseline: 12.0047x; 2.3628x over previous
#include <cuda_runtime.h>
#include <cuda_fp16.h>
#include <math.h>
#include <stdint.h>

#define BB 2
#define NN 2048
#define CC 1024
#define HH 16
#define DD 64
#define FF 4096
#define TT (BB*NN)          // 4096 tokens

// ---------------- scratch (device globals) ----------------
__device__ __half g_xn  [(size_t)TT*CC];
__device__ __half g_qkv [(size_t)TT*3*CC];
__device__ __half g_y   [(size_t)TT*CC];
__device__ float  g_x1  [(size_t)TT*CC];
__device__ __half g_xn2 [(size_t)TT*CC];
__device__ __half g_h   [(size_t)TT*FF];
__device__ __half g_wqkv[(size_t)CC*3*CC];
__device__ __half g_wp  [(size_t)CC*CC];
__device__ __half g_w1  [(size_t)CC*FF];
__device__ __half g_w2  [(size_t)FF*CC];

// ---------------- helpers ----------------
__device__ __forceinline__ uint32_t smem_u32(const void* p) {
    return (uint32_t)__cvta_generic_to_shared(p);
}

__device__ __forceinline__ void mma_f16(float4& d,
    uint32_t a0, uint32_t a1, uint32_t a2, uint32_t a3, uint32_t b0, uint32_t b1)
{
    asm volatile(
        "mma.sync.aligned.m16n8k16.row.col.f32.f16.f16.f32 "
        "{%0,%1,%2,%3}, {%4,%5,%6,%7}, {%8,%9}, {%0,%1,%2,%3};\n"
        : "+f"(d.x), "+f"(d.y), "+f"(d.z), "+f"(d.w)
        : "r"(a0), "r"(a1), "r"(a2), "r"(a3), "r"(b0), "r"(b1));
}

__device__ __forceinline__ void ldsm_x4(uint32_t& r0, uint32_t& r1, uint32_t& r2, uint32_t& r3,
                                        uint32_t addr) {
    asm volatile("ldmatrix.sync.aligned.m8n8.x4.shared.b16 {%0,%1,%2,%3}, [%4];"
        : "=r"(r0), "=r"(r1), "=r"(r2), "=r"(r3) : "r"(addr));
}
__device__ __forceinline__ void ldsm_x4_t(uint32_t& r0, uint32_t& r1, uint32_t& r2, uint32_t& r3,
                                          uint32_t addr) {
    asm volatile("ldmatrix.sync.aligned.m8n8.x4.trans.shared.b16 {%0,%1,%2,%3}, [%4];"
        : "=r"(r0), "=r"(r1), "=r"(r2), "=r"(r3) : "r"(addr));
}

__device__ __forceinline__ void cp16(void* smem_dst, const void* gsrc) {
    uint32_t d = smem_u32(smem_dst);
    asm volatile("cp.async.cg.shared.global [%0], [%1], 16;\n" :: "r"(d), "l"(gsrc));
}
__device__ __forceinline__ void cp_commit() { asm volatile("cp.async.commit_group;\n"); }
__device__ __forceinline__ void cp_wait0() { asm volatile("cp.async.wait_group 0;\n"); }
__device__ __forceinline__ void cp_wait1() { asm volatile("cp.async.wait_group 1;\n"); }

__device__ __forceinline__ uint32_t pkh2(float x, float y) {
    __half2 h = __floats2half2_rn(x, y);
    return *(uint32_t*)&h;
}

__device__ __forceinline__ float blockReduceSum256(float v) {
    __shared__ float sm[8];
    #pragma unroll
    for (int o = 16; o > 0; o >>= 1) v += __shfl_xor_sync(0xffffffffu, v, o);
    __syncthreads();
    if ((threadIdx.x & 31) == 0) sm[threadIdx.x >> 5] = v;
    __syncthreads();
    float t = 0.f;
    #pragma unroll
    for (int i = 0; i < 8; i++) t += sm[i];
    return t;
}

// ---------------- weight conversion fp32 -> fp16 (with pack/scale) ----------------
__global__ __launch_bounds__(256) void conv_pack_kernel(
    const float* __restrict__ in, __half* __restrict__ out,
    int cols, int ldo, int colofs, float scale, int n4)
{
    int i = blockIdx.x * 256 + threadIdx.x;
    if (i >= n4) return;
    float4 v = ((const float4*)in)[i];
    int c4 = cols >> 2;
    int row = i / c4;
    int col = (i - row * c4) * 4;
    __half2* o = (__half2*)(out + (size_t)row * ldo + colofs + col);
    o[0] = __floats2half2_rn(v.x * scale, v.y * scale);
    o[1] = __floats2half2_rn(v.z * scale, v.w * scale);
}

// ---------------- layernorm: fp32 in -> fp16 out ----------------
__global__ __launch_bounds__(256) void layernorm_kernel(
    const float* __restrict__ x, const float* __restrict__ gamma,
    const float* __restrict__ beta, __half* __restrict__ out)
{
    const size_t row = (size_t)blockIdx.x * CC;
    const int c = threadIdx.x * 4;
    float4 v = *(const float4*)(x + row + c);

    float s = v.x + v.y + v.z + v.w;
    s = blockReduceSum256(s);
    float mu = s * (1.0f / CC);

    float dx = v.x - mu, dy = v.y - mu, dz = v.z - mu, dw = v.w - mu;
    float ss = dx*dx + dy*dy + dz*dz + dw*dw;
    ss = blockReduceSum256(ss);
    float rstd = rsqrtf(ss * (1.0f / CC) + 1e-6f);

    float4 g = *(const float4*)(gamma + c);
    float4 b = *(const float4*)(beta + c);
    __half2* o = (__half2*)(out + row + c);
    o[0] = __floats2half2_rn(dx * rstd * g.x + b.x, dy * rstd * g.y + b.y);
    o[1] = __floats2half2_rn(dz * rstd * g.z + b.z, dw * rstd * g.w + b.w);
}

// ---------------- fp16 tensor-core GEMM 128x128x32, cp.async double-buffered ----
// out = epi(A@B): +bias, gelu, +res; writes Cf (fp32) or Ch (fp16)
__global__ __launch_bounds__(256) void h_gemm_kernel(
    const __half* __restrict__ A, const __half* __restrict__ Bm,
    const float* __restrict__ bias, const float* __restrict__ res,
    float* __restrict__ Cf, __half* __restrict__ Ch,
    int N, int K, int do_gelu)
{
    __shared__ __half As[2][128][40];
    __shared__ __half Bs[2][32][136];

    const int tid = threadIdx.x;
    const int lane = tid & 31;
    const int wid = tid >> 5;
    const int bx = blockIdx.x, by = blockIdx.y;
    const int m0w = (wid >> 2) * 64;
    const int n0w = (wid & 3) * 32;
    const int idx = lane & 7;
    const int sel = (lane >> 3) & 3;

    float4 acc[4][4];
    #pragma unroll
    for (int i = 0; i < 4; i++)
        #pragma unroll
        for (int j = 0; j < 4; j++) acc[i][j] = make_float4(0.f, 0.f, 0.f, 0.f);

    auto loadTile = [&](int k0, int buf) {
        #pragma unroll
        for (int i = 0; i < 2; i++) {
            int c = tid + i * 256;           // 512 chunks of 8 halfs for A (128x32)
            int r = c >> 2, c8 = (c & 3) * 8;
            cp16(&As[buf][r][c8], A + (size_t)(by * 128 + r) * K + k0 + c8);
        }
        #pragma unroll
        for (int i = 0; i < 2; i++) {
            int c = tid + i * 256;           // 512 chunks for B (32x128)
            int r = c >> 4, c8 = (c & 15) * 8;
            cp16(&Bs[buf][r][c8], Bm + (size_t)(k0 + r) * N + bx * 128 + c8);
        }
        cp_commit();
    };

    const int KT = K >> 5;
    loadTile(0, 0);
    int buf = 0;
    for (int kt = 0; kt < KT; kt++) {
        if (kt + 1 < KT) { loadTile((kt + 1) << 5, buf ^ 1); cp_wait1(); }
        else cp_wait0();
        __syncthreads();

        #pragma unroll
        for (int kk = 0; kk < 32; kk += 16) {
            uint32_t af[4][4];
            #pragma unroll
            for (int im = 0; im < 4; im++)
                ldsm_x4(af[im][0], af[im][1], af[im][2], af[im][3],
                        smem_u32(&As[buf][m0w + im * 16 + (lane & 15)][kk + ((lane >> 4) << 3)]));
            uint32_t bf[4][2];
            #pragma unroll
            for (int inp = 0; inp < 4; inp += 2)
                ldsm_x4_t(bf[inp][0], bf[inp][1], bf[inp + 1][0], bf[inp + 1][1],
                          smem_u32(&Bs[buf][kk + (sel & 1) * 8 + idx][n0w + inp * 8 + (sel >> 1) * 8]));
            #pragma unroll
            for (int im = 0; im < 4; im++)
                #pragma unroll
                for (int in = 0; in < 4; in++)
                    mma_f16(acc[im][in], af[im][0], af[im][1], af[im][2], af[im][3],
                            bf[in][0], bf[in][1]);
        }
        __syncthreads();
        buf ^= 1;
    }

    // epilogue
    #pragma unroll
    for (int im = 0; im < 4; im++) {
        #pragma unroll
        for (int in = 0; in < 4; in++) {
            int row = by * 128 + m0w + im * 16 + (lane >> 2);
            int col = bx * 128 + n0w + in * 8 + (lane & 3) * 2;
            #pragma unroll
            for (int half = 0; half < 2; half++) {
                int r = row + half * 8;
                float v0 = half ? acc[im][in].z : acc[im][in].x;
                float v1 = half ? acc[im][in].w : acc[im][in].y;
                if (bias) { v0 += bias[col]; v1 += bias[col + 1]; }
                if (do_gelu) {
                    v0 = 0.5f * v0 * (1.0f + erff(v0 * 0.70710678118654752f));
                    v1 = 0.5f * v1 * (1.0f + erff(v1 * 0.70710678118654752f));
                }
                if (res) {
                    v0 += res[(size_t)r * N + col];
                    v1 += res[(size_t)r * N + col + 1];
                }
                if (Ch) {
                    *(__half2*)(Ch + (size_t)r * N + col) = __floats2half2_rn(v0, v1);
                } else {
                    *(float2*)(Cf + (size_t)r * N + col) = make_float2(v0, v1);
                }
            }
        }
    }
}

// ---------------- fused flash attention ----------------
// grid (NN/128, B*H), 256 thr (8 warps x 16 rows). qkv: [T][3C] fp16, y: [T][C] fp16
__global__ __launch_bounds__(256) void flash_kernel(
    const __half* __restrict__ qkv, __half* __restrict__ y)
{
    extern __shared__ __half fsm[];
    __half (*Qs)[72] = (__half(*)[72])fsm;                      // 128x72
    __half (*Ks)[72] = (__half(*)[72])(fsm + 128 * 72);         // 2 x 128x72
    __half (*Vs)[72] = (__half(*)[72])(fsm + 3 * 128 * 72);     // 2 x 128x72

    const int bh = blockIdx.y;
    const int b = bh >> 4, h = bh & 15;
    const int n0 = blockIdx.x * 128;
    const int tid = threadIdx.x;
    const int lane = tid & 31;
    const int wid = tid >> 5;
    const int idx = lane & 7;
    const int sel = (lane >> 3) & 3;

    const size_t tok0 = (size_t)b * NN;
    const __half* qb = qkv + h * DD;                 // q at col offset 0
    const __half* kb = qkv + CC + h * DD;            // k at col offset C
    const __half* vb = qkv + 2 * CC + h * DD;        // v at col offset 2C

    // load Q tile (128 x 64)
    #pragma unroll
    for (int i = 0; i < 4; i++) {
        int c = tid + i * 256;               // 1024 chunks
        int r = c >> 3, c8 = (c & 7) * 8;
        cp16(&Qs[r][c8], qb + (tok0 + n0 + r) * (3 * CC) + c8);
    }
    cp_commit();

    auto loadKV = [&](int m0, int buf) {
        #pragma unroll
        for (int i = 0; i < 4; i++) {
            int c = tid + i * 256;
            int r = c >> 3, c8 = (c & 7) * 8;
            cp16(&Ks[buf * 128 + r][c8], kb + (tok0 + m0 + r) * (3 * CC) + c8);
        }
        #pragma unroll
        for (int i = 0; i < 4; i++) {
            int c = tid + i * 256;
            int r = c >> 3, c8 = (c & 7) * 8;
            cp16(&Vs[buf * 128 + r][c8], vb + (tok0 + m0 + r) * (3 * CC) + c8);
        }
        cp_commit();
    };

    loadKV(0, 0);

    uint32_t aq[4][4];                 // Q fragments, 4 k16-steps over D=64
    float4 acc_o[8];                   // O accum: 16 rows x 64 cols per warp
    #pragma unroll
    for (int i = 0; i < 8; i++) acc_o[i] = make_float4(0.f, 0.f, 0.f, 0.f);
    float mrow[2] = {-1e30f, -1e30f};
    float lpart[2] = {0.f, 0.f};

    int buf = 0;
    const int NTILE = NN / 128;        // 16
    for (int jt = 0; jt < NTILE; jt++) {
        if (jt + 1 < NTILE) { loadKV((jt + 1) * 128, buf ^ 1); cp_wait1(); }
        else cp_wait0();
        __syncthreads();

        if (jt == 0) {
            #pragma unroll
            for (int kd = 0; kd < 4; kd++)
                ldsm_x4(aq[kd][0], aq[kd][1], aq[kd][2], aq[kd][3],
                        smem_u32(&Qs[wid * 16 + (lane & 15)][kd * 16 + ((lane >> 4) << 3)]));
        }

        // S = Q @ K^T  (16 rows x 128 cols per warp)
        float4 acc_s[16];
        #pragma unroll
        for (int i = 0; i < 16; i++) acc_s[i] = make_float4(0.f, 0.f, 0.f, 0.f);
        #pragma unroll
        for (int kd = 0; kd < 4; kd++) {
            #pragma unroll
            for (int inp = 0; inp < 16; inp += 2) {
                uint32_t b0, b1, b2, b3;
                // non-trans: Ks is [m][d] = n-major for the B operand (k=d, n=m)
                ldsm_x4(b0, b1, b2, b3,
                        smem_u32(&Ks[buf * 128 + inp * 8 + (sel >> 1) * 8 + idx][kd * 16 + (sel & 1) * 8]));
                mma_f16(acc_s[inp],     aq[kd][0], aq[kd][1], aq[kd][2], aq[kd][3], b0, b1);
                mma_f16(acc_s[inp + 1], aq[kd][0], aq[kd][1], aq[kd][2], aq[kd][3], b2, b3);
            }
        }

        // online softmax
        float mx0 = -1e30f, mx1 = -1e30f;
        #pragma unroll
        for (int i = 0; i < 16; i++) {
            mx0 = fmaxf(mx0, fmaxf(acc_s[i].x, acc_s[i].y));
            mx1 = fmaxf(mx1, fmaxf(acc_s[i].z, acc_s[i].w));
        }
        mx0 = fmaxf(mx0, __shfl_xor_sync(0xffffffffu, mx0, 1));
        mx0 = fmaxf(mx0, __shfl_xor_sync(0xffffffffu, mx0, 2));
        mx1 = fmaxf(mx1, __shfl_xor_sync(0xffffffffu, mx1, 1));
        mx1 = fmaxf(mx1, __shfl_xor_sync(0xffffffffu, mx1, 2));
        float mn0 = fmaxf(mrow[0], mx0), mn1 = fmaxf(mrow[1], mx1);
        float al0 = __expf(mrow[0] - mn0), al1 = __expf(mrow[1] - mn1);
        mrow[0] = mn0; mrow[1] = mn1;

        float ps0 = 0.f, ps1 = 0.f;
        #pragma unroll
        for (int i = 0; i < 16; i++) {
            acc_s[i].x = __expf(acc_s[i].x - mn0);
            acc_s[i].y = __expf(acc_s[i].y - mn0);
            acc_s[i].z = __expf(acc_s[i].z - mn1);
            acc_s[i].w = __expf(acc_s[i].w - mn1);
            ps0 += acc_s[i].x + acc_s[i].y;
            ps1 += acc_s[i].z + acc_s[i].w;
        }
        lpart[0] = lpart[0] * al0 + ps0;
        lpart[1] = lpart[1] * al1 + ps1;
        #pragma unroll
        for (int i = 0; i < 8; i++) {
            acc_o[i].x *= al0; acc_o[i].y *= al0;
            acc_o[i].z *= al1; acc_o[i].w *= al1;
        }

        // O += P @ V   (k = 128 keys, n = 64 dims)
        #pragma unroll
        for (int ks = 0; ks < 8; ks++) {
            uint32_t a0 = pkh2(acc_s[2 * ks].x,     acc_s[2 * ks].y);
            uint32_t a1 = pkh2(acc_s[2 * ks].z,     acc_s[2 * ks].w);
            uint32_t a2 = pkh2(acc_s[2 * ks + 1].x, acc_s[2 * ks + 1].y);
            uint32_t a3 = pkh2(acc_s[2 * ks + 1].z, acc_s[2 * ks + 1].w);
            #pragma unroll
            for (int dp = 0; dp < 4; dp++) {
                uint32_t b0, b1, b2, b3;
                // trans: Vs is [m][d] = k-major for the B operand (k=m, n=d)
                ldsm_x4_t(b0, b1, b2, b3,
                          smem_u32(&Vs[buf * 128 + ks * 16 + (sel & 1) * 8 + idx][dp * 16 + (sel >> 1) * 8]));
                mma_f16(acc_o[2 * dp],     a0, a1, a2, a3, b0, b1);
                mma_f16(acc_o[2 * dp + 1], a0, a1, a2, a3, b2, b3);
            }
        }
        __syncthreads();
        buf ^= 1;
    }

    float ls0 = lpart[0];
    ls0 += __shfl_xor_sync(0xffffffffu, ls0, 1);
    ls0 += __shfl_xor_sync(0xffffffffu, ls0, 2);
    float ls1 = lpart[1];
    ls1 += __shfl_xor_sync(0xffffffffu, ls1, 1);
    ls1 += __shfl_xor_sync(0xffffffffu, ls1, 2);
    float inv0 = 1.0f / ls0, inv1 = 1.0f / ls1;

    const int r0 = lane >> 2;
    #pragma unroll
    for (int df = 0; df < 8; df++) {
        int col = h * DD + df * 8 + (lane & 3) * 2;
        int n = n0 + wid * 16 + r0;
        *(__half2*)(y + (tok0 + n) * CC + col) =
            __floats2half2_rn(acc_o[df].x * inv0, acc_o[df].y * inv0);
        *(__half2*)(y + (tok0 + n + 8) * CC + col) =
            __floats2half2_rn(acc_o[df].z * inv1, acc_o[df].w * inv1);
    }
}

// ---------------- launch ----------------
extern "C" void kernel_launch(void* const* d_in, const int* in_sizes, int n_in,
                              void* d_out, int out_size)
{
    const float* x      = (const float*)d_in[0];
    const float* Wq     = (const float*)d_in[1];
    const float* Wk     = (const float*)d_in[2];
    const float* Wv     = (const float*)d_in[3];
    const float* Wp     = (const float*)d_in[4];
    const float* bp     = (const float*)d_in[5];
    const float* W1     = (const float*)d_in[6];
    const float* b1     = (const float*)d_in[7];
    const float* W2     = (const float*)d_in[8];
    const float* b2     = (const float*)d_in[9];
    const float* gamma1 = (const float*)d_in[10];
    const float* beta1  = (const float*)d_in[11];
    const float* gamma2 = (const float*)d_in[12];
    const float* beta2  = (const float*)d_in[13];
    float* out = (float*)d_out;

    __half *xn, *qkv, *y, *xn2, *hb, *wqkv, *wp, *w1, *w2;
    float *x1;
    cudaGetSymbolAddress((void**)&xn,   g_xn);
    cudaGetSymbolAddress((void**)&qkv,  g_qkv);
    cudaGetSymbolAddress((void**)&y,    g_y);
    cudaGetSymbolAddress((void**)&x1,   g_x1);
    cudaGetSymbolAddress((void**)&xn2,  g_xn2);
    cudaGetSymbolAddress((void**)&hb,   g_h);
    cudaGetSymbolAddress((void**)&wqkv, g_wqkv);
    cudaGetSymbolAddress((void**)&wp,   g_wp);
    cudaGetSymbolAddress((void**)&w1,   g_w1);
    cudaGetSymbolAddress((void**)&w2,   g_w2);

    const int FLASH_SMEM = 5 * 128 * 72 * (int)sizeof(__half);   // 92160 B
    cudaFuncSetAttribute(flash_kernel, cudaFuncAttributeMaxDynamicSharedMemorySize, FLASH_SMEM);

    // 0) convert weights to fp16 (qscale folded into Wq)
    {
        int n4a = CC * CC / 4, n4b = CC * FF / 4;
        conv_pack_kernel<<<(n4a + 255) / 256, 256>>>(Wq, wqkv, CC, 3 * CC, 0,      0.125f, n4a);
        conv_pack_kernel<<<(n4a + 255) / 256, 256>>>(Wk, wqkv, CC, 3 * CC, CC,     1.0f,   n4a);
        conv_pack_kernel<<<(n4a + 255) / 256, 256>>>(Wv, wqkv, CC, 3 * CC, 2 * CC, 1.0f,   n4a);
        conv_pack_kernel<<<(n4a + 255) / 256, 256>>>(Wp, wp, CC, CC, 0, 1.0f, n4a);
        conv_pack_kernel<<<(n4b + 255) / 256, 256>>>(W1, w1, FF, FF, 0, 1.0f, n4b);
        conv_pack_kernel<<<(n4b + 255) / 256, 256>>>(W2, w2, CC, CC, 0, 1.0f, n4b);
    }

    // 1) LN1 -> fp16
    layernorm_kernel<<<TT, 256>>>(x, gamma1, beta1, xn);

    // 2) fused QKV projection: [T,1024] @ [1024,3072]
    {
        dim3 g(3 * CC / 128, TT / 128);
        h_gemm_kernel<<<g, 256>>>(xn, wqkv, nullptr, nullptr, nullptr, qkv, 3 * CC, CC, 0);
    }

    // 3) fused flash attention
    {
        dim3 g(NN / 128, BB * HH);
        flash_kernel<<<g, 256, FLASH_SMEM>>>(qkv, y);
    }

    // 4) output projection + residual: x1 = x + y@Wp + bp (fp32 out)
    {
        dim3 g(CC / 128, TT / 128);
        h_gemm_kernel<<<g, 256>>>(y, wp, bp, x, x1, nullptr, CC, CC, 0);
    }

    // 5) LN2 -> fp16
    layernorm_kernel<<<TT, 256>>>(x1, gamma2, beta2, xn2);

    // 6) MLP
    {
        dim3 g(FF / 128, TT / 128);
        h_gemm_kernel<<<g, 256>>>(xn2, w1, b1, nullptr, nullptr, hb, FF, CC, 1);
    }
    {
        dim3 g(CC / 128, TT / 128);
        h_gemm_kernel<<<g, 256>>>(hb, w2, b2, x1, out, nullptr, CC, FF, 0);
    }
}

// round 7
// speedup vs baseline: 12.3103x; 1.0255x over previous
#include <cuda_runtime.h>
#include <cuda_fp16.h>
#include <math.h>
#include <stdint.h>

#define BB 2
#define NN 2048
#define CC 1024
#define HH 16
#define DD 64
#define FF 4096
#define TT (BB*NN)          // 4096 tokens

// ---------------- scratch (device globals) ----------------
__device__ __half g_xn  [(size_t)TT*CC];
__device__ __half g_qkv [(size_t)TT*3*CC];
__device__ __half g_y   [(size_t)TT*CC];
__device__ float  g_x1  [(size_t)TT*CC];
__device__ __half g_xn2 [(size_t)TT*CC];
__device__ __half g_h   [(size_t)TT*FF];
__device__ __half g_wqkv[(size_t)CC*3*CC];
__device__ __half g_wp  [(size_t)CC*CC];
__device__ __half g_w1  [(size_t)CC*FF];
__device__ __half g_w2  [(size_t)FF*CC];

// ---------------- helpers ----------------
__device__ __forceinline__ uint32_t smem_u32(const void* p) {
    return (uint32_t)__cvta_generic_to_shared(p);
}

__device__ __forceinline__ void mma_f16(float4& d,
    uint32_t a0, uint32_t a1, uint32_t a2, uint32_t a3, uint32_t b0, uint32_t b1)
{
    asm volatile(
        "mma.sync.aligned.m16n8k16.row.col.f32.f16.f16.f32 "
        "{%0,%1,%2,%3}, {%4,%5,%6,%7}, {%8,%9}, {%0,%1,%2,%3};\n"
        : "+f"(d.x), "+f"(d.y), "+f"(d.z), "+f"(d.w)
        : "r"(a0), "r"(a1), "r"(a2), "r"(a3), "r"(b0), "r"(b1));
}

__device__ __forceinline__ void ldsm_x4(uint32_t& r0, uint32_t& r1, uint32_t& r2, uint32_t& r3,
                                        uint32_t addr) {
    asm volatile("ldmatrix.sync.aligned.m8n8.x4.shared.b16 {%0,%1,%2,%3}, [%4];"
        : "=r"(r0), "=r"(r1), "=r"(r2), "=r"(r3) : "r"(addr));
}
__device__ __forceinline__ void ldsm_x4_t(uint32_t& r0, uint32_t& r1, uint32_t& r2, uint32_t& r3,
                                          uint32_t addr) {
    asm volatile("ldmatrix.sync.aligned.m8n8.x4.trans.shared.b16 {%0,%1,%2,%3}, [%4];"
        : "=r"(r0), "=r"(r1), "=r"(r2), "=r"(r3) : "r"(addr));
}
__device__ __forceinline__ void ldsm_x2_t(uint32_t& r0, uint32_t& r1, uint32_t addr) {
    asm volatile("ldmatrix.sync.aligned.m8n8.x2.trans.shared.b16 {%0,%1}, [%2];"
        : "=r"(r0), "=r"(r1) : "r"(addr));
}

__device__ __forceinline__ void cp16(void* smem_dst, const void* gsrc) {
    uint32_t d = smem_u32(smem_dst);
    asm volatile("cp.async.cg.shared.global [%0], [%1], 16;\n" :: "r"(d), "l"(gsrc));
}
__device__ __forceinline__ void cp_commit() { asm volatile("cp.async.commit_group;\n"); }
__device__ __forceinline__ void cp_wait0() { asm volatile("cp.async.wait_group 0;\n"); }
__device__ __forceinline__ void cp_wait1() { asm volatile("cp.async.wait_group 1;\n"); }

__device__ __forceinline__ uint32_t pkh2(float x, float y) {
    __half2 h = __floats2half2_rn(x, y);
    return *(uint32_t*)&h;
}
__device__ __forceinline__ uint32_t ex2h2(uint32_t a) {
    uint32_t d;
    asm("ex2.approx.f16x2 %0, %1;" : "=r"(d) : "r"(a));
    return d;
}

#define L2E 1.4426950408889634f

__device__ __forceinline__ float blockReduceSum256(float v) {
    __shared__ float sm[8];
    #pragma unroll
    for (int o = 16; o > 0; o >>= 1) v += __shfl_xor_sync(0xffffffffu, v, o);
    __syncthreads();
    if ((threadIdx.x & 31) == 0) sm[threadIdx.x >> 5] = v;
    __syncthreads();
    float t = 0.f;
    #pragma unroll
    for (int i = 0; i < 8; i++) t += sm[i];
    return t;
}

// ---------------- weight conversion fp32 -> fp16 (pack/scale) ----------------
__global__ __launch_bounds__(256) void conv_pack_kernel(
    const float* __restrict__ in, __half* __restrict__ out,
    int cols, int ldo, int colofs, float scale, int n4)
{
    int i = blockIdx.x * 256 + threadIdx.x;
    if (i >= n4) return;
    float4 v = ((const float4*)in)[i];
    int c4 = cols >> 2;
    int row = i / c4;
    int col = (i - row * c4) * 4;
    __half2* o = (__half2*)(out + (size_t)row * ldo + colofs + col);
    o[0] = __floats2half2_rn(v.x * scale, v.y * scale);
    o[1] = __floats2half2_rn(v.z * scale, v.w * scale);
}

// ---------------- layernorm: fp32 in -> fp16 out ----------------
__global__ __launch_bounds__(256) void layernorm_kernel(
    const float* __restrict__ x, const float* __restrict__ gamma,
    const float* __restrict__ beta, __half* __restrict__ out)
{
    const size_t row = (size_t)blockIdx.x * CC;
    const int c = threadIdx.x * 4;
    float4 v = *(const float4*)(x + row + c);

    float s = v.x + v.y + v.z + v.w;
    s = blockReduceSum256(s);
    float mu = s * (1.0f / CC);

    float dx = v.x - mu, dy = v.y - mu, dz = v.z - mu, dw = v.w - mu;
    float ss = dx*dx + dy*dy + dz*dz + dw*dw;
    ss = blockReduceSum256(ss);
    float rstd = rsqrtf(ss * (1.0f / CC) + 1e-6f);

    float4 g = *(const float4*)(gamma + c);
    float4 b = *(const float4*)(beta + c);
    __half2* o = (__half2*)(out + row + c);
    o[0] = __floats2half2_rn(dx * rstd * g.x + b.x, dy * rstd * g.y + b.y);
    o[1] = __floats2half2_rn(dz * rstd * g.z + b.z, dw * rstd * g.w + b.w);
}

// ---------------- fp16 GEMM 128x128x64, cp.async double-buffered ----------------
// A [M][K] fp16 row-major, B [K][N] fp16 row-major
// smem: As [2*128][72], Bs [2*64][136]  -> 71680 B dynamic
#define GEMM_SMEM (2*128*72*2 + 2*64*136*2)

__global__ __launch_bounds__(256) void h_gemm_kernel(
    const __half* __restrict__ A, const __half* __restrict__ Bm,
    const float* __restrict__ bias, const float* __restrict__ res,
    float* __restrict__ Cf, __half* __restrict__ Ch,
    int N, int K, int do_gelu)
{
    extern __shared__ char gsm[];
    __half (*As)[72]  = (__half(*)[72])gsm;                      // [2*128][72]
    __half (*Bs)[136] = (__half(*)[136])(gsm + 2 * 128 * 72 * 2); // [2*64][136]

    const int tid = threadIdx.x;
    const int lane = tid & 31;
    const int wid = tid >> 5;
    const int bx = blockIdx.x, by = blockIdx.y;
    const int m0w = (wid >> 2) * 64;
    const int n0w = (wid & 3) * 32;
    const int idx = lane & 7;
    const int sel = (lane >> 3) & 3;

    float4 acc[4][4];
    #pragma unroll
    for (int i = 0; i < 4; i++)
        #pragma unroll
        for (int j = 0; j < 4; j++) acc[i][j] = make_float4(0.f, 0.f, 0.f, 0.f);

    auto loadChunk = [&](int k0, int buf) {
        #pragma unroll
        for (int i = 0; i < 4; i++) {
            int c = tid + i * 256;          // 1024 chunks for A (128x64)
            int r = c >> 3, c8 = (c & 7) * 8;
            cp16(&As[buf * 128 + r][c8], A + (size_t)(by * 128 + r) * K + k0 + c8);
        }
        #pragma unroll
        for (int i = 0; i < 4; i++) {
            int c = tid + i * 256;          // 1024 chunks for B (64x128)
            int r = c >> 4, c8 = (c & 15) * 8;
            cp16(&Bs[buf * 64 + r][c8], Bm + (size_t)(k0 + r) * N + bx * 128 + c8);
        }
        cp_commit();
    };

    const int KT = K >> 6;
    loadChunk(0, 0);
    int buf = 0;
    for (int kt = 0; kt < KT; kt++) {
        if (kt + 1 < KT) { loadChunk((kt + 1) << 6, buf ^ 1); cp_wait1(); }
        else cp_wait0();
        __syncthreads();

        #pragma unroll
        for (int kk = 0; kk < 64; kk += 16) {
            uint32_t af[4][4];
            #pragma unroll
            for (int im = 0; im < 4; im++)
                ldsm_x4(af[im][0], af[im][1], af[im][2], af[im][3],
                        smem_u32(&As[buf * 128 + m0w + im * 16 + (lane & 15)][kk + ((lane >> 4) << 3)]));
            uint32_t bf[4][2];
            #pragma unroll
            for (int inp = 0; inp < 4; inp += 2)
                ldsm_x4_t(bf[inp][0], bf[inp][1], bf[inp + 1][0], bf[inp + 1][1],
                          smem_u32(&Bs[buf * 64 + kk + (sel & 1) * 8 + idx][n0w + inp * 8 + (sel >> 1) * 8]));
            #pragma unroll
            for (int im = 0; im < 4; im++)
                #pragma unroll
                for (int in = 0; in < 4; in++)
                    mma_f16(acc[im][in], af[im][0], af[im][1], af[im][2], af[im][3],
                            bf[in][0], bf[in][1]);
        }
        __syncthreads();
        buf ^= 1;
    }

    // epilogue
    #pragma unroll
    for (int im = 0; im < 4; im++) {
        #pragma unroll
        for (int in = 0; in < 4; in++) {
            int row = by * 128 + m0w + im * 16 + (lane >> 2);
            int col = bx * 128 + n0w + in * 8 + (lane & 3) * 2;
            #pragma unroll
            for (int half = 0; half < 2; half++) {
                int r = row + half * 8;
                float v0 = half ? acc[im][in].z : acc[im][in].x;
                float v1 = half ? acc[im][in].w : acc[im][in].y;
                if (bias) { v0 += bias[col]; v1 += bias[col + 1]; }
                if (do_gelu) {
                    v0 = 0.5f * v0 * (1.0f + erff(v0 * 0.70710678118654752f));
                    v1 = 0.5f * v1 * (1.0f + erff(v1 * 0.70710678118654752f));
                }
                if (res) {
                    v0 += res[(size_t)r * N + col];
                    v1 += res[(size_t)r * N + col + 1];
                }
                if (Ch) {
                    *(__half2*)(Ch + (size_t)r * N + col) = __floats2half2_rn(v0, v1);
                } else {
                    *(float2*)(Cf + (size_t)r * N + col) = make_float2(v0, v1);
                }
            }
        }
    }
}

// ---------------- fused flash attention (mma.sync, h2-exp, l-in-MMA) ----------------
// grid (NN/128, B*H), 256 thr. qkv: [T][3C] fp16, y: [T][C] fp16
// V smem col 64 = 1.0 (ones column) -> row sum l accumulates in extra MMA accum.
__global__ __launch_bounds__(256) void flash_kernel(
    const __half* __restrict__ qkv, __half* __restrict__ y)
{
    extern __shared__ __half fsm[];
    __half (*Qs)[72] = (__half(*)[72])fsm;                      // 128x72
    __half (*Ks)[72] = (__half(*)[72])(fsm + 128 * 72);         // 2 x 128x72
    __half (*Vs)[72] = (__half(*)[72])(fsm + 3 * 128 * 72);     // 2 x 128x72

    const int bh = blockIdx.y;
    const int b = bh >> 4, h = bh & 15;
    const int n0 = blockIdx.x * 128;
    const int tid = threadIdx.x;
    const int lane = tid & 31;
    const int wid = tid >> 5;
    const int idx = lane & 7;
    const int sel = (lane >> 3) & 3;

    const size_t tok0 = (size_t)b * NN;
    const __half* qb = qkv + h * DD;
    const __half* kb = qkv + CC + h * DD;
    const __half* vb = qkv + 2 * CC + h * DD;

    #pragma unroll
    for (int i = 0; i < 4; i++) {
        int c = tid + i * 256;
        int r = c >> 3, c8 = (c & 7) * 8;
        cp16(&Qs[r][c8], qb + (tok0 + n0 + r) * (3 * CC) + c8);
    }
    cp_commit();

    auto loadKV = [&](int m0, int buf) {
        #pragma unroll
        for (int i = 0; i < 4; i++) {
            int c = tid + i * 256;
            int r = c >> 3, c8 = (c & 7) * 8;
            cp16(&Ks[buf * 128 + r][c8], kb + (tok0 + m0 + r) * (3 * CC) + c8);
        }
        #pragma unroll
        for (int i = 0; i < 4; i++) {
            int c = tid + i * 256;
            int r = c >> 3, c8 = (c & 7) * 8;
            cp16(&Vs[buf * 128 + r][c8], vb + (tok0 + m0 + r) * (3 * CC) + c8);
        }
        cp_commit();
    };

    loadKV(0, 0);

    // ones column at V col 64, zeros 65-71 (both buffers, cols untouched by cp.async)
    {
        __half* p = &Vs[tid][64];       // tid = 0..255 covers both buffers' rows
        p[0] = __float2half(1.0f);
        #pragma unroll
        for (int j = 1; j < 8; j++) p[j] = __float2half(0.0f);
    }

    uint32_t aq[4][4];
    float4 acc_o[8];
    float4 acc_l = make_float4(0.f, 0.f, 0.f, 0.f);
    #pragma unroll
    for (int i = 0; i < 8; i++) acc_o[i] = make_float4(0.f, 0.f, 0.f, 0.f);
    float mrow[2] = {-1e30f, -1e30f};

    int buf = 0;
    const int NTILE = NN / 128;
    for (int jt = 0; jt < NTILE; jt++) {
        if (jt + 1 < NTILE) { loadKV((jt + 1) * 128, buf ^ 1); cp_wait1(); }
        else cp_wait0();
        __syncthreads();

        if (jt == 0) {
            #pragma unroll
            for (int kd = 0; kd < 4; kd++)
                ldsm_x4(aq[kd][0], aq[kd][1], aq[kd][2], aq[kd][3],
                        smem_u32(&Qs[wid * 16 + (lane & 15)][kd * 16 + ((lane >> 4) << 3)]));
        }

        // S = Q @ K^T
        float4 acc_s[16];
        #pragma unroll
        for (int i = 0; i < 16; i++) acc_s[i] = make_float4(0.f, 0.f, 0.f, 0.f);
        #pragma unroll
        for (int kd = 0; kd < 4; kd++) {
            #pragma unroll
            for (int inp = 0; inp < 16; inp += 2) {
                uint32_t b0, b1, b2, b3;
                ldsm_x4(b0, b1, b2, b3,
                        smem_u32(&Ks[buf * 128 + inp * 8 + (sel >> 1) * 8 + idx][kd * 16 + (sel & 1) * 8]));
                mma_f16(acc_s[inp],     aq[kd][0], aq[kd][1], aq[kd][2], aq[kd][3], b0, b1);
                mma_f16(acc_s[inp + 1], aq[kd][0], aq[kd][1], aq[kd][2], aq[kd][3], b2, b3);
            }
        }

        // row max (fp32)
        float mx0 = -1e30f, mx1 = -1e30f;
        #pragma unroll
        for (int i = 0; i < 16; i++) {
            mx0 = fmaxf(mx0, fmaxf(acc_s[i].x, acc_s[i].y));
            mx1 = fmaxf(mx1, fmaxf(acc_s[i].z, acc_s[i].w));
        }
        mx0 = fmaxf(mx0, __shfl_xor_sync(0xffffffffu, mx0, 1));
        mx0 = fmaxf(mx0, __shfl_xor_sync(0xffffffffu, mx0, 2));
        mx1 = fmaxf(mx1, __shfl_xor_sync(0xffffffffu, mx1, 1));
        mx1 = fmaxf(mx1, __shfl_xor_sync(0xffffffffu, mx1, 2));
        float mn0 = fmaxf(mrow[0], mx0), mn1 = fmaxf(mrow[1], mx1);
        float al0 = exp2f((mrow[0] - mn0) * L2E), al1 = exp2f((mrow[1] - mn1) * L2E);
        mrow[0] = mn0; mrow[1] = mn1;
        const float nm0 = -mn0 * L2E, nm1 = -mn1 * L2E;

        // rescale O and l
        #pragma unroll
        for (int i = 0; i < 8; i++) {
            acc_o[i].x *= al0; acc_o[i].y *= al0;
            acc_o[i].z *= al1; acc_o[i].w *= al1;
        }
        acc_l.x *= al0; acc_l.y *= al0; acc_l.z *= al1; acc_l.w *= al1;

        // P in fp16 via ex2.approx.f16x2, then O += P @ V (V col 64 = ones -> l)
        #pragma unroll
        for (int ks = 0; ks < 8; ks++) {
            uint32_t a0 = ex2h2(pkh2(fmaf(acc_s[2 * ks].x, L2E, nm0),
                                     fmaf(acc_s[2 * ks].y, L2E, nm0)));
            uint32_t a1 = ex2h2(pkh2(fmaf(acc_s[2 * ks].z, L2E, nm1),
                                     fmaf(acc_s[2 * ks].w, L2E, nm1)));
            uint32_t a2 = ex2h2(pkh2(fmaf(acc_s[2 * ks + 1].x, L2E, nm0),
                                     fmaf(acc_s[2 * ks + 1].y, L2E, nm0)));
            uint32_t a3 = ex2h2(pkh2(fmaf(acc_s[2 * ks + 1].z, L2E, nm1),
                                     fmaf(acc_s[2 * ks + 1].w, L2E, nm1)));
            #pragma unroll
            for (int dp = 0; dp < 4; dp++) {
                uint32_t b0, b1, b2, b3;
                ldsm_x4_t(b0, b1, b2, b3,
                          smem_u32(&Vs[buf * 128 + ks * 16 + (sel & 1) * 8 + idx][dp * 16 + (sel >> 1) * 8]));
                mma_f16(acc_o[2 * dp],     a0, a1, a2, a3, b0, b1);
                mma_f16(acc_o[2 * dp + 1], a0, a1, a2, a3, b2, b3);
            }
            {
                uint32_t b0, b1;
                ldsm_x2_t(b0, b1,
                          smem_u32(&Vs[buf * 128 + ks * 16 + ((lane >> 3) & 1) * 8 + idx][64]));
                mma_f16(acc_l, a0, a1, a2, a3, b0, b1);
            }
        }
        __syncthreads();
        buf ^= 1;
    }

    // l lives in acc_l.x (rows r0) / acc_l.z (rows r0+8) of quad-leader lanes
    float l0 = __shfl_sync(0xffffffffu, acc_l.x, lane & 0x1C);
    float l1 = __shfl_sync(0xffffffffu, acc_l.z, lane & 0x1C);
    float inv0 = 1.0f / l0, inv1 = 1.0f / l1;

    const int r0 = lane >> 2;
    #pragma unroll
    for (int df = 0; df < 8; df++) {
        int col = h * DD + df * 8 + (lane & 3) * 2;
        int n = n0 + wid * 16 + r0;
        *(__half2*)(y + (tok0 + n) * CC + col) =
            __floats2half2_rn(acc_o[df].x * inv0, acc_o[df].y * inv0);
        *(__half2*)(y + (tok0 + n + 8) * CC + col) =
            __floats2half2_rn(acc_o[df].z * inv1, acc_o[df].w * inv1);
    }
}

// ---------------- launch ----------------
extern "C" void kernel_launch(void* const* d_in, const int* in_sizes, int n_in,
                              void* d_out, int out_size)
{
    const float* x      = (const float*)d_in[0];
    const float* Wq     = (const float*)d_in[1];
    const float* Wk     = (const float*)d_in[2];
    const float* Wv     = (const float*)d_in[3];
    const float* Wp     = (const float*)d_in[4];
    const float* bp     = (const float*)d_in[5];
    const float* W1     = (const float*)d_in[6];
    const float* b1     = (const float*)d_in[7];
    const float* W2     = (const float*)d_in[8];
    const float* b2     = (const float*)d_in[9];
    const float* gamma1 = (const float*)d_in[10];
    const float* beta1  = (const float*)d_in[11];
    const float* gamma2 = (const float*)d_in[12];
    const float* beta2  = (const float*)d_in[13];
    float* out = (float*)d_out;

    __half *xn, *qkv, *y, *xn2, *hb, *wqkv, *wp, *w1, *w2;
    float *x1;
    cudaGetSymbolAddress((void**)&xn,   g_xn);
    cudaGetSymbolAddress((void**)&qkv,  g_qkv);
    cudaGetSymbolAddress((void**)&y,    g_y);
    cudaGetSymbolAddress((void**)&x1,   g_x1);
    cudaGetSymbolAddress((void**)&xn2,  g_xn2);
    cudaGetSymbolAddress((void**)&hb,   g_h);
    cudaGetSymbolAddress((void**)&wqkv, g_wqkv);
    cudaGetSymbolAddress((void**)&wp,   g_wp);
    cudaGetSymbolAddress((void**)&w1,   g_w1);
    cudaGetSymbolAddress((void**)&w2,   g_w2);

    const int FLASH_SMEM = 5 * 128 * 72 * (int)sizeof(__half);   // 92160 B
    cudaFuncSetAttribute(flash_kernel, cudaFuncAttributeMaxDynamicSharedMemorySize, FLASH_SMEM);
    cudaFuncSetAttribute(h_gemm_kernel, cudaFuncAttributeMaxDynamicSharedMemorySize, GEMM_SMEM);

    // 0) convert weights to fp16 (qscale folded into Wq)
    {
        int n4a = CC * CC / 4, n4b = CC * FF / 4;
        conv_pack_kernel<<<(n4a + 255) / 256, 256>>>(Wq, wqkv, CC, 3 * CC, 0,      0.125f, n4a);
        conv_pack_kernel<<<(n4a + 255) / 256, 256>>>(Wk, wqkv, CC, 3 * CC, CC,     1.0f,   n4a);
        conv_pack_kernel<<<(n4a + 255) / 256, 256>>>(Wv, wqkv, CC, 3 * CC, 2 * CC, 1.0f,   n4a);
        conv_pack_kernel<<<(n4a + 255) / 256, 256>>>(Wp, wp, CC, CC, 0, 1.0f, n4a);
        conv_pack_kernel<<<(n4b + 255) / 256, 256>>>(W1, w1, FF, FF, 0, 1.0f, n4b);
        conv_pack_kernel<<<(n4b + 255) / 256, 256>>>(W2, w2, CC, CC, 0, 1.0f, n4b);
    }

    // 1) LN1 -> fp16
    layernorm_kernel<<<TT, 256>>>(x, gamma1, beta1, xn);

    // 2) fused QKV projection: [T,C] @ [C,3C]
    {
        dim3 g(3 * CC / 128, TT / 128);
        h_gemm_kernel<<<g, 256, GEMM_SMEM>>>(xn, wqkv, nullptr, nullptr, nullptr, qkv,
                                             3 * CC, CC, 0);
    }

    // 3) fused flash attention
    {
        dim3 g(NN / 128, BB * HH);
        flash_kernel<<<g, 256, FLASH_SMEM>>>(qkv, y);
    }

    // 4) output projection + residual: x1 = x + y@Wp + bp (fp32 out)
    {
        dim3 g(CC / 128, TT / 128);
        h_gemm_kernel<<<g, 256, GEMM_SMEM>>>(y, wp, bp, x, x1, nullptr, CC, CC, 0);
    }

    // 5) LN2 -> fp16
    layernorm_kernel<<<TT, 256>>>(x1, gamma2, beta2, xn2);

    // 6) MLP
    {
        dim3 g(FF / 128, TT / 128);
        h_gemm_kernel<<<g, 256, GEMM_SMEM>>>(xn2, w1, b1, nullptr, nullptr, hb, FF, CC, 1);
    }
    {
        dim3 g(CC / 128, TT / 128);
        h_gemm_kernel<<<g, 256, GEMM_SMEM>>>(hb, w2, b2, x1, out, nullptr, CC, FF, 0);
    }
}

// round 9
// speedup vs baseline: 12.5349x; 1.0182x over previous
#include <cuda_runtime.h>
#include <cuda_fp16.h>
#include <math.h>
#include <stdint.h>

#define BB 2
#define NN 2048
#define CC 1024
#define HH 16
#define DD 64
#define FF 4096
#define TT (BB*NN)          // 4096 tokens

// ---------------- scratch (device globals) ----------------
__device__ __half g_xn  [(size_t)TT*CC];
__device__ __half g_qkv [(size_t)TT*3*CC];
__device__ __half g_y   [(size_t)TT*CC];
__device__ float  g_x1  [(size_t)TT*CC];
__device__ __half g_xn2 [(size_t)TT*CC];
__device__ __half g_h   [(size_t)TT*FF];
__device__ __half g_wqkv[(size_t)CC*3*CC];
__device__ __half g_wp  [(size_t)CC*CC];
__device__ __half g_w1  [(size_t)CC*FF];
__device__ __half g_w2  [(size_t)FF*CC];

// ---------------- helpers ----------------
__device__ __forceinline__ uint32_t smem_u32(const void* p) {
    return (uint32_t)__cvta_generic_to_shared(p);
}

__device__ __forceinline__ void mma_f16(float4& d,
    uint32_t a0, uint32_t a1, uint32_t a2, uint32_t a3, uint32_t b0, uint32_t b1)
{
    asm volatile(
        "mma.sync.aligned.m16n8k16.row.col.f32.f16.f16.f32 "
        "{%0,%1,%2,%3}, {%4,%5,%6,%7}, {%8,%9}, {%0,%1,%2,%3};\n"
        : "+f"(d.x), "+f"(d.y), "+f"(d.z), "+f"(d.w)
        : "r"(a0), "r"(a1), "r"(a2), "r"(a3), "r"(b0), "r"(b1));
}

__device__ __forceinline__ void ldsm_x4(uint32_t& r0, uint32_t& r1, uint32_t& r2, uint32_t& r3,
                                        uint32_t addr) {
    asm volatile("ldmatrix.sync.aligned.m8n8.x4.shared.b16 {%0,%1,%2,%3}, [%4];"
        : "=r"(r0), "=r"(r1), "=r"(r2), "=r"(r3) : "r"(addr));
}
__device__ __forceinline__ void ldsm_x4_t(uint32_t& r0, uint32_t& r1, uint32_t& r2, uint32_t& r3,
                                          uint32_t addr) {
    asm volatile("ldmatrix.sync.aligned.m8n8.x4.trans.shared.b16 {%0,%1,%2,%3}, [%4];"
        : "=r"(r0), "=r"(r1), "=r"(r2), "=r"(r3) : "r"(addr));
}
__device__ __forceinline__ void ldsm_x2_t(uint32_t& r0, uint32_t& r1, uint32_t addr) {
    asm volatile("ldmatrix.sync.aligned.m8n8.x2.trans.shared.b16 {%0,%1}, [%2];"
        : "=r"(r0), "=r"(r1) : "r"(addr));
}

__device__ __forceinline__ void cp16(void* smem_dst, const void* gsrc) {
    uint32_t d = smem_u32(smem_dst);
    asm volatile("cp.async.cg.shared.global [%0], [%1], 16;\n" :: "r"(d), "l"(gsrc));
}
__device__ __forceinline__ void cp_commit() { asm volatile("cp.async.commit_group;\n"); }
__device__ __forceinline__ void cp_wait0() { asm volatile("cp.async.wait_group 0;\n"); }
__device__ __forceinline__ void cp_wait1() { asm volatile("cp.async.wait_group 1;\n"); }

__device__ __forceinline__ uint32_t pkh2(float x, float y) {
    __half2 h = __floats2half2_rn(x, y);
    return *(uint32_t*)&h;
}
__device__ __forceinline__ uint32_t ex2h2(uint32_t a) {
    uint32_t d;
    asm("ex2.approx.f16x2 %0, %1;" : "=r"(d) : "r"(a));
    return d;
}

#define L2E 1.4426950408889634f

__device__ __forceinline__ float blockReduceSum256(float v) {
    __shared__ float sm[8];
    #pragma unroll
    for (int o = 16; o > 0; o >>= 1) v += __shfl_xor_sync(0xffffffffu, v, o);
    __syncthreads();
    if ((threadIdx.x & 31) == 0) sm[threadIdx.x >> 5] = v;
    __syncthreads();
    float t = 0.f;
    #pragma unroll
    for (int i = 0; i < 8; i++) t += sm[i];
    return t;
}

// ---------------- fused weight conversion: all 6 weights in one launch --------------
// block ranges (256 thr, 256 float4 per block):
//  [0,1024)      Wq  -> wqkv col 0     (scale 0.125)
//  [1024,2048)   Wk  -> wqkv col CC
//  [2048,3072)   Wv  -> wqkv col 2CC
//  [3072,4096)   Wp  -> wp
//  [4096,8192)   W1  -> w1
//  [8192,12288)  W2  -> w2
__global__ __launch_bounds__(256) void conv_all_kernel(
    const float* __restrict__ Wq, const float* __restrict__ Wk,
    const float* __restrict__ Wv, const float* __restrict__ Wp,
    const float* __restrict__ W1, const float* __restrict__ W2,
    __half* __restrict__ wqkv, __half* __restrict__ wp,
    __half* __restrict__ w1, __half* __restrict__ w2)
{
    const int blk = blockIdx.x;
    const float* in;
    __half* out;
    int cols, ldo, colofs, i0;
    float scale = 1.0f;
    if (blk < 4096) {
        cols = CC;
        if (blk < 1024)      { in = Wq; out = wqkv; ldo = 3 * CC; colofs = 0;      i0 = 0;    scale = 0.125f; }
        else if (blk < 2048) { in = Wk; out = wqkv; ldo = 3 * CC; colofs = CC;     i0 = 1024; }
        else if (blk < 3072) { in = Wv; out = wqkv; ldo = 3 * CC; colofs = 2 * CC; i0 = 2048; }
        else                 { in = Wp; out = wp;   ldo = CC;     colofs = 0;      i0 = 3072; }
    } else if (blk < 8192)   { in = W1; out = w1; cols = FF; ldo = FF; colofs = 0; i0 = 4096; }
    else                     { in = W2; out = w2; cols = CC; ldo = CC; colofs = 0; i0 = 8192; }

    int i = (blk - i0) * 256 + threadIdx.x;
    float4 v = ((const float4*)in)[i];
    int c4 = cols >> 2;
    int row = i / c4;
    int col = (i - row * c4) * 4;
    __half2* o = (__half2*)(out + (size_t)row * ldo + colofs + col);
    o[0] = __floats2half2_rn(v.x * scale, v.y * scale);
    o[1] = __floats2half2_rn(v.z * scale, v.w * scale);
}

// ---------------- layernorm: fp32 in -> fp16 out ----------------
__global__ __launch_bounds__(256) void layernorm_kernel(
    const float* __restrict__ x, const float* __restrict__ gamma,
    const float* __restrict__ beta, __half* __restrict__ out)
{
    const size_t row = (size_t)blockIdx.x * CC;
    const int c = threadIdx.x * 4;
    float4 v = *(const float4*)(x + row + c);

    float s = v.x + v.y + v.z + v.w;
    s = blockReduceSum256(s);
    float mu = s * (1.0f / CC);

    float dx = v.x - mu, dy = v.y - mu, dz = v.z - mu, dw = v.w - mu;
    float ss = dx*dx + dy*dy + dz*dz + dw*dw;
    ss = blockReduceSum256(ss);
    float rstd = rsqrtf(ss * (1.0f / CC) + 1e-6f);

    float4 g = *(const float4*)(gamma + c);
    float4 b = *(const float4*)(beta + c);
    __half2* o = (__half2*)(out + row + c);
    o[0] = __floats2half2_rn(dx * rstd * g.x + b.x, dy * rstd * g.y + b.y);
    o[1] = __floats2half2_rn(dz * rstd * g.z + b.z, dw * rstd * g.w + b.w);
}

// ---------------- fp16 GEMM 128x128x64, cp.async double-buffered, 2 CTA/SM ------
// A [M][K] fp16 row-major, B [K][N] fp16 row-major
// smem: As [2*128][72], Bs [2*64][136]  -> 71680 B dynamic
#define GEMM_SMEM (2*128*72*2 + 2*64*136*2)

__global__ __launch_bounds__(256, 2) void h_gemm_kernel(
    const __half* __restrict__ A, const __half* __restrict__ Bm,
    const float* __restrict__ bias, const float* __restrict__ res,
    float* __restrict__ Cf, __half* __restrict__ Ch,
    int N, int K, int do_gelu)
{
    extern __shared__ char gsm[];
    __half (*As)[72]  = (__half(*)[72])gsm;                       // [2*128][72]
    __half (*Bs)[136] = (__half(*)[136])(gsm + 2 * 128 * 72 * 2); // [2*64][136]

    const int tid = threadIdx.x;
    const int lane = tid & 31;
    const int wid = tid >> 5;
    const int bx = blockIdx.x, by = blockIdx.y;
    const int m0w = (wid >> 2) * 64;
    const int n0w = (wid & 3) * 32;
    const int idx = lane & 7;
    const int sel = (lane >> 3) & 3;

    float4 acc[4][4];
    #pragma unroll
    for (int i = 0; i < 4; i++)
        #pragma unroll
        for (int j = 0; j < 4; j++) acc[i][j] = make_float4(0.f, 0.f, 0.f, 0.f);

    auto loadChunk = [&](int k0, int buf) {
        #pragma unroll
        for (int i = 0; i < 4; i++) {
            int c = tid + i * 256;          // 1024 chunks for A (128x64)
            int r = c >> 3, c8 = (c & 7) * 8;
            cp16(&As[buf * 128 + r][c8], A + (size_t)(by * 128 + r) * K + k0 + c8);
        }
        #pragma unroll
        for (int i = 0; i < 4; i++) {
            int c = tid + i * 256;          // 1024 chunks for B (64x128)
            int r = c >> 4, c8 = (c & 15) * 8;
            cp16(&Bs[buf * 64 + r][c8], Bm + (size_t)(k0 + r) * N + bx * 128 + c8);
        }
        cp_commit();
    };

    const int KT = K >> 6;
    loadChunk(0, 0);
    int buf = 0;
    for (int kt = 0; kt < KT; kt++) {
        if (kt + 1 < KT) { loadChunk((kt + 1) << 6, buf ^ 1); cp_wait1(); }
        else cp_wait0();
        __syncthreads();

        #pragma unroll
        for (int kk = 0; kk < 64; kk += 16) {
            uint32_t af[4][4];
            #pragma unroll
            for (int im = 0; im < 4; im++)
                ldsm_x4(af[im][0], af[im][1], af[im][2], af[im][3],
                        smem_u32(&As[buf * 128 + m0w + im * 16 + (lane & 15)][kk + ((lane >> 4) << 3)]));
            uint32_t bf[4][2];
            #pragma unroll
            for (int inp = 0; inp < 4; inp += 2)
                ldsm_x4_t(bf[inp][0], bf[inp][1], bf[inp + 1][0], bf[inp + 1][1],
                          smem_u32(&Bs[buf * 64 + kk + (sel & 1) * 8 + idx][n0w + inp * 8 + (sel >> 1) * 8]));
            #pragma unroll
            for (int im = 0; im < 4; im++)
                #pragma unroll
                for (int in = 0; in < 4; in++)
                    mma_f16(acc[im][in], af[im][0], af[im][1], af[im][2], af[im][3],
                            bf[in][0], bf[in][1]);
        }
        __syncthreads();
        buf ^= 1;
    }

    // epilogue
    #pragma unroll
    for (int im = 0; im < 4; im++) {
        #pragma unroll
        for (int in = 0; in < 4; in++) {
            int row = by * 128 + m0w + im * 16 + (lane >> 2);
            int col = bx * 128 + n0w + in * 8 + (lane & 3) * 2;
            #pragma unroll
            for (int half = 0; half < 2; half++) {
                int r = row + half * 8;
                float v0 = half ? acc[im][in].z : acc[im][in].x;
                float v1 = half ? acc[im][in].w : acc[im][in].y;
                if (bias) { v0 += bias[col]; v1 += bias[col + 1]; }
                if (do_gelu) {
                    v0 = 0.5f * v0 * (1.0f + erff(v0 * 0.70710678118654752f));
                    v1 = 0.5f * v1 * (1.0f + erff(v1 * 0.70710678118654752f));
                }
                if (res) {
                    v0 += res[(size_t)r * N + col];
                    v1 += res[(size_t)r * N + col + 1];
                }
                if (Ch) {
                    *(__half2*)(Ch + (size_t)r * N + col) = __floats2half2_rn(v0, v1);
                } else {
                    *(float2*)(Cf + (size_t)r * N + col) = make_float2(v0, v1);
                }
            }
        }
    }
}

// ---------------- fused flash attention (mma.sync, h2-exp, l-in-MMA) ----------------
// grid (NN/128, B*H), 256 thr. qkv: [T][3C] fp16, y: [T][C] fp16
// V smem col 64 = 1.0 (ones column) -> row sum l accumulates in extra MMA accum.
__global__ __launch_bounds__(256) void flash_kernel(
    const __half* __restrict__ qkv, __half* __restrict__ y)
{
    extern __shared__ __half fsm[];
    __half (*Qs)[72] = (__half(*)[72])fsm;                      // 128x72
    __half (*Ks)[72] = (__half(*)[72])(fsm + 128 * 72);         // 2 x 128x72
    __half (*Vs)[72] = (__half(*)[72])(fsm + 3 * 128 * 72);     // 2 x 128x72

    const int bh = blockIdx.y;
    const int b = bh >> 4, h = bh & 15;
    const int n0 = blockIdx.x * 128;
    const int tid = threadIdx.x;
    const int lane = tid & 31;
    const int wid = tid >> 5;
    const int idx = lane & 7;
    const int sel = (lane >> 3) & 3;

    const size_t tok0 = (size_t)b * NN;
    const __half* qb = qkv + h * DD;
    const __half* kb = qkv + CC + h * DD;
    const __half* vb = qkv + 2 * CC + h * DD;

    // Q tile: its own cp.async group (g0)
    #pragma unroll
    for (int i = 0; i < 4; i++) {
        int c = tid + i * 256;
        int r = c >> 3, c8 = (c & 7) * 8;
        cp16(&Qs[r][c8], qb + (tok0 + n0 + r) * (3 * CC) + c8);
    }
    cp_commit();

    auto loadKV = [&](int m0, int buf) {
        #pragma unroll
        for (int i = 0; i < 4; i++) {
            int c = tid + i * 256;
            int r = c >> 3, c8 = (c & 7) * 8;
            cp16(&Ks[buf * 128 + r][c8], kb + (tok0 + m0 + r) * (3 * CC) + c8);
        }
        #pragma unroll
        for (int i = 0; i < 4; i++) {
            int c = tid + i * 256;
            int r = c >> 3, c8 = (c & 7) * 8;
            cp16(&Vs[buf * 128 + r][c8], vb + (tok0 + m0 + r) * (3 * CC) + c8);
        }
        cp_commit();
    };

    loadKV(0, 0);   // g1

    // ones column at V col 64, zeros 65-71 (both buffers; cols untouched by cp.async)
    {
        __half* p = &Vs[tid][64];       // tid = 0..255 covers both buffers' rows
        p[0] = __float2half(1.0f);
        #pragma unroll
        for (int j = 1; j < 8; j++) p[j] = __float2half(0.0f);
    }

    // hoist Q fragment load: wait g0 only (g1 still in flight)
    cp_wait1();
    __syncthreads();
    uint32_t aq[4][4];
    #pragma unroll
    for (int kd = 0; kd < 4; kd++)
        ldsm_x4(aq[kd][0], aq[kd][1], aq[kd][2], aq[kd][3],
                smem_u32(&Qs[wid * 16 + (lane & 15)][kd * 16 + ((lane >> 4) << 3)]));

    float4 acc_o[8];
    float4 acc_l = make_float4(0.f, 0.f, 0.f, 0.f);
    #pragma unroll
    for (int i = 0; i < 8; i++) acc_o[i] = make_float4(0.f, 0.f, 0.f, 0.f);
    float mrow[2] = {-1e30f, -1e30f};

    int buf = 0;
    const int NTILE = NN / 128;
    for (int jt = 0; jt < NTILE; jt++) {
        if (jt + 1 < NTILE) { loadKV((jt + 1) * 128, buf ^ 1); cp_wait1(); }
        else cp_wait0();
        __syncthreads();

        // S = Q @ K^T
        float4 acc_s[16];
        #pragma unroll
        for (int i = 0; i < 16; i++) acc_s[i] = make_float4(0.f, 0.f, 0.f, 0.f);
        #pragma unroll
        for (int kd = 0; kd < 4; kd++) {
            #pragma unroll
            for (int inp = 0; inp < 16; inp += 2) {
                uint32_t b0, b1, b2, b3;
                ldsm_x4(b0, b1, b2, b3,
                        smem_u32(&Ks[buf * 128 + inp * 8 + (sel >> 1) * 8 + idx][kd * 16 + (sel & 1) * 8]));
                mma_f16(acc_s[inp],     aq[kd][0], aq[kd][1], aq[kd][2], aq[kd][3], b0, b1);
                mma_f16(acc_s[inp + 1], aq[kd][0], aq[kd][1], aq[kd][2], aq[kd][3], b2, b3);
            }
        }

        // row max (fp32)
        float mx0 = -1e30f, mx1 = -1e30f;
        #pragma unroll
        for (int i = 0; i < 16; i++) {
            mx0 = fmaxf(mx0, fmaxf(acc_s[i].x, acc_s[i].y));
            mx1 = fmaxf(mx1, fmaxf(acc_s[i].z, acc_s[i].w));
        }
        mx0 = fmaxf(mx0, __shfl_xor_sync(0xffffffffu, mx0, 1));
        mx0 = fmaxf(mx0, __shfl_xor_sync(0xffffffffu, mx0, 2));
        mx1 = fmaxf(mx1, __shfl_xor_sync(0xffffffffu, mx1, 1));
        mx1 = fmaxf(mx1, __shfl_xor_sync(0xffffffffu, mx1, 2));
        float mn0 = fmaxf(mrow[0], mx0), mn1 = fmaxf(mrow[1], mx1);
        float al0 = exp2f((mrow[0] - mn0) * L2E), al1 = exp2f((mrow[1] - mn1) * L2E);
        mrow[0] = mn0; mrow[1] = mn1;
        const float nm0 = -mn0 * L2E, nm1 = -mn1 * L2E;

        // rescale O and l
        #pragma unroll
        for (int i = 0; i < 8; i++) {
            acc_o[i].x *= al0; acc_o[i].y *= al0;
            acc_o[i].z *= al1; acc_o[i].w *= al1;
        }
        acc_l.x *= al0; acc_l.y *= al0; acc_l.z *= al1; acc_l.w *= al1;

        // P in fp16 via ex2.approx.f16x2, then O += P @ V (V col 64 = ones -> l)
        #pragma unroll
        for (int ks = 0; ks < 8; ks++) {
            uint32_t a0 = ex2h2(pkh2(fmaf(acc_s[2 * ks].x, L2E, nm0),
                                     fmaf(acc_s[2 * ks].y, L2E, nm0)));
            uint32_t a1 = ex2h2(pkh2(fmaf(acc_s[2 * ks].z, L2E, nm1),
                                     fmaf(acc_s[2 * ks].w, L2E, nm1)));
            uint32_t a2 = ex2h2(pkh2(fmaf(acc_s[2 * ks + 1].x, L2E, nm0),
                                     fmaf(acc_s[2 * ks + 1].y, L2E, nm0)));
            uint32_t a3 = ex2h2(pkh2(fmaf(acc_s[2 * ks + 1].z, L2E, nm1),
                                     fmaf(acc_s[2 * ks + 1].w, L2E, nm1)));
            #pragma unroll
            for (int dp = 0; dp < 4; dp++) {
                uint32_t b0, b1, b2, b3;
                ldsm_x4_t(b0, b1, b2, b3,
                          smem_u32(&Vs[buf * 128 + ks * 16 + (sel & 1) * 8 + idx][dp * 16 + (sel >> 1) * 8]));
                mma_f16(acc_o[2 * dp],     a0, a1, a2, a3, b0, b1);
                mma_f16(acc_o[2 * dp + 1], a0, a1, a2, a3, b2, b3);
            }
            {
                uint32_t b0, b1;
                ldsm_x2_t(b0, b1,
                          smem_u32(&Vs[buf * 128 + ks * 16 + ((lane >> 3) & 1) * 8 + idx][64]));
                mma_f16(acc_l, a0, a1, a2, a3, b0, b1);
            }
        }
        __syncthreads();
        buf ^= 1;
    }

    // l lives in acc_l.x (rows r0) / acc_l.z (rows r0+8) of quad-leader lanes
    float l0 = __shfl_sync(0xffffffffu, acc_l.x, lane & 0x1C);
    float l1 = __shfl_sync(0xffffffffu, acc_l.z, lane & 0x1C);
    float inv0 = 1.0f / l0, inv1 = 1.0f / l1;

    const int r0 = lane >> 2;
    #pragma unroll
    for (int df = 0; df < 8; df++) {
        int col = h * DD + df * 8 + (lane & 3) * 2;
        int n = n0 + wid * 16 + r0;
        *(__half2*)(y + (tok0 + n) * CC + col) =
            __floats2half2_rn(acc_o[df].x * inv0, acc_o[df].y * inv0);
        *(__half2*)(y + (tok0 + n + 8) * CC + col) =
            __floats2half2_rn(acc_o[df].z * inv1, acc_o[df].w * inv1);
    }
}

// ---------------- launch ----------------
extern "C" void kernel_launch(void* const* d_in, const int* in_sizes, int n_in,
                              void* d_out, int out_size)
{
    const float* x      = (const float*)d_in[0];
    const float* Wq     = (const float*)d_in[1];
    const float* Wk     = (const float*)d_in[2];
    const float* Wv     = (const float*)d_in[3];
    const float* Wp     = (const float*)d_in[4];
    const float* bp     = (const float*)d_in[5];
    const float* W1     = (const float*)d_in[6];
    const float* b1     = (const float*)d_in[7];
    const float* W2     = (const float*)d_in[8];
    const float* b2     = (const float*)d_in[9];
    const float* gamma1 = (const float*)d_in[10];
    const float* beta1  = (const float*)d_in[11];
    const float* gamma2 = (const float*)d_in[12];
    const float* beta2  = (const float*)d_in[13];
    float* out = (float*)d_out;

    __half *xn, *qkv, *y, *xn2, *hb, *wqkv, *wp, *w1, *w2;
    float *x1;
    cudaGetSymbolAddress((void**)&xn,   g_xn);
    cudaGetSymbolAddress((void**)&qkv,  g_qkv);
    cudaGetSymbolAddress((void**)&y,    g_y);
    cudaGetSymbolAddress((void**)&x1,   g_x1);
    cudaGetSymbolAddress((void**)&xn2,  g_xn2);
    cudaGetSymbolAddress((void**)&hb,   g_h);
    cudaGetSymbolAddress((void**)&wqkv, g_wqkv);
    cudaGetSymbolAddress((void**)&wp,   g_wp);
    cudaGetSymbolAddress((void**)&w1,   g_w1);
    cudaGetSymbolAddress((void**)&w2,   g_w2);

    const int FLASH_SMEM = 5 * 128 * 72 * (int)sizeof(__half);   // 92160 B
    cudaFuncSetAttribute(flash_kernel, cudaFuncAttributeMaxDynamicSharedMemorySize, FLASH_SMEM);
    cudaFuncSetAttribute(h_gemm_kernel, cudaFuncAttributeMaxDynamicSharedMemorySize, GEMM_SMEM);

    // 0) all weight conversions in ONE launch (qscale folded into Wq)
    conv_all_kernel<<<12288, 256>>>(Wq, Wk, Wv, Wp, W1, W2, wqkv, wp, w1, w2);

    // 1) LN1 -> fp16
    layernorm_kernel<<<TT, 256>>>(x, gamma1, beta1, xn);

    // 2) fused QKV projection: [T,C] @ [C,3C]
    {
        dim3 g(3 * CC / 128, TT / 128);
        h_gemm_kernel<<<g, 256, GEMM_SMEM>>>(xn, wqkv, nullptr, nullptr, nullptr, qkv,
                                             3 * CC, CC, 0);
    }

    // 3) fused flash attention
    {
        dim3 g(NN / 128, BB * HH);
        flash_kernel<<<g, 256, FLASH_SMEM>>>(qkv, y);
    }

    // 4) output projection + residual: x1 = x + y@Wp + bp (fp32 out)
    {
        dim3 g(CC / 128, TT / 128);
        h_gemm_kernel<<<g, 256, GEMM_SMEM>>>(y, wp, bp, x, x1, nullptr, CC, CC, 0);
    }

    // 5) LN2 -> fp16
    layernorm_kernel<<<TT, 256>>>(x1, gamma2, beta2, xn2);

    // 6) MLP
    {
        dim3 g(FF / 128, TT / 128);
        h_gemm_kernel<<<g, 256, GEMM_SMEM>>>(xn2, w1, b1, nullptr, nullptr, hb, FF, CC, 1);
    }
    {
        dim3 g(CC / 128, TT / 128);
        h_gemm_kernel<<<g, 256, GEMM_SMEM>>>(hb, w2, b2, x1, out, nullptr, CC, FF, 0);
    }
}

// round 10
// speedup vs baseline: 13.0456x; 1.0407x over previous
#include <cuda_runtime.h>
#include <cuda_fp16.h>
#include <math.h>
#include <stdint.h>

#define BB 2
#define NN 2048
#define CC 1024
#define HH 16
#define DD 64
#define FF 4096
#define TT (BB*NN)          // 4096 tokens

// ---------------- scratch (device globals) ----------------
__device__ __half g_xn  [(size_t)TT*CC];
__device__ __half g_qkv [(size_t)TT*3*CC];
__device__ __half g_y   [(size_t)TT*CC];
__device__ float  g_x1  [(size_t)TT*CC];
__device__ __half g_xn2 [(size_t)TT*CC];
__device__ __half g_h   [(size_t)TT*FF];
__device__ __half g_wqkv[(size_t)CC*3*CC];
__device__ __half g_wp  [(size_t)CC*CC];
__device__ __half g_w1  [(size_t)CC*FF];
__device__ __half g_w2  [(size_t)FF*CC];

// ---------------- helpers ----------------
__device__ __forceinline__ uint32_t smem_u32(const void* p) {
    return (uint32_t)__cvta_generic_to_shared(p);
}

__device__ __forceinline__ void mma_f16(float4& d,
    uint32_t a0, uint32_t a1, uint32_t a2, uint32_t a3, uint32_t b0, uint32_t b1)
{
    asm volatile(
        "mma.sync.aligned.m16n8k16.row.col.f32.f16.f16.f32 "
        "{%0,%1,%2,%3}, {%4,%5,%6,%7}, {%8,%9}, {%0,%1,%2,%3};\n"
        : "+f"(d.x), "+f"(d.y), "+f"(d.z), "+f"(d.w)
        : "r"(a0), "r"(a1), "r"(a2), "r"(a3), "r"(b0), "r"(b1));
}

__device__ __forceinline__ void ldsm_x4(uint32_t& r0, uint32_t& r1, uint32_t& r2, uint32_t& r3,
                                        uint32_t addr) {
    asm volatile("ldmatrix.sync.aligned.m8n8.x4.shared.b16 {%0,%1,%2,%3}, [%4];"
        : "=r"(r0), "=r"(r1), "=r"(r2), "=r"(r3) : "r"(addr));
}
__device__ __forceinline__ void ldsm_x4_t(uint32_t& r0, uint32_t& r1, uint32_t& r2, uint32_t& r3,
                                          uint32_t addr) {
    asm volatile("ldmatrix.sync.aligned.m8n8.x4.trans.shared.b16 {%0,%1,%2,%3}, [%4];"
        : "=r"(r0), "=r"(r1), "=r"(r2), "=r"(r3) : "r"(addr));
}
__device__ __forceinline__ void ldsm_x2_t(uint32_t& r0, uint32_t& r1, uint32_t addr) {
    asm volatile("ldmatrix.sync.aligned.m8n8.x2.trans.shared.b16 {%0,%1}, [%2];"
        : "=r"(r0), "=r"(r1) : "r"(addr));
}

__device__ __forceinline__ void cp16(void* smem_dst, const void* gsrc) {
    uint32_t d = smem_u32(smem_dst);
    asm volatile("cp.async.cg.shared.global [%0], [%1], 16;\n" :: "r"(d), "l"(gsrc));
}
__device__ __forceinline__ void cp_commit() { asm volatile("cp.async.commit_group;\n"); }
__device__ __forceinline__ void cp_wait0() { asm volatile("cp.async.wait_group 0;\n"); }
__device__ __forceinline__ void cp_wait1() { asm volatile("cp.async.wait_group 1;\n"); }

__device__ __forceinline__ uint32_t pkh2(float x, float y) {
    __half2 h = __floats2half2_rn(x, y);
    return *(uint32_t*)&h;
}
__device__ __forceinline__ uint32_t ex2h2(uint32_t a) {
    uint32_t d;
    asm("ex2.approx.f16x2 %0, %1;" : "=r"(d) : "r"(a));
    return d;
}

#define L2E 1.4426950408889634f

__device__ __forceinline__ float blockReduceSum256(float v) {
    __shared__ float sm[8];
    #pragma unroll
    for (int o = 16; o > 0; o >>= 1) v += __shfl_xor_sync(0xffffffffu, v, o);
    __syncthreads();
    if ((threadIdx.x & 31) == 0) sm[threadIdx.x >> 5] = v;
    __syncthreads();
    float t = 0.f;
    #pragma unroll
    for (int i = 0; i < 8; i++) t += sm[i];
    return t;
}

// ---------------- fused weight conversion: all 6 weights in one launch --------------
__global__ __launch_bounds__(256) void conv_all_kernel(
    const float* __restrict__ Wq, const float* __restrict__ Wk,
    const float* __restrict__ Wv, const float* __restrict__ Wp,
    const float* __restrict__ W1, const float* __restrict__ W2,
    __half* __restrict__ wqkv, __half* __restrict__ wp,
    __half* __restrict__ w1, __half* __restrict__ w2)
{
    const int blk = blockIdx.x;
    const float* in;
    __half* out;
    int cols, ldo, colofs, i0;
    float scale = 1.0f;
    if (blk < 4096) {
        cols = CC;
        if (blk < 1024)      { in = Wq; out = wqkv; ldo = 3 * CC; colofs = 0;      i0 = 0;    scale = 0.125f; }
        else if (blk < 2048) { in = Wk; out = wqkv; ldo = 3 * CC; colofs = CC;     i0 = 1024; }
        else if (blk < 3072) { in = Wv; out = wqkv; ldo = 3 * CC; colofs = 2 * CC; i0 = 2048; }
        else                 { in = Wp; out = wp;   ldo = CC;     colofs = 0;      i0 = 3072; }
    } else if (blk < 8192)   { in = W1; out = w1; cols = FF; ldo = FF; colofs = 0; i0 = 4096; }
    else                     { in = W2; out = w2; cols = CC; ldo = CC; colofs = 0; i0 = 8192; }

    int i = (blk - i0) * 256 + threadIdx.x;
    float4 v = ((const float4*)in)[i];
    int c4 = cols >> 2;
    int row = i / c4;
    int col = (i - row * c4) * 4;
    __half2* o = (__half2*)(out + (size_t)row * ldo + colofs + col);
    o[0] = __floats2half2_rn(v.x * scale, v.y * scale);
    o[1] = __floats2half2_rn(v.z * scale, v.w * scale);
}

// ---------------- layernorm: fp32 in -> fp16 out ----------------
__global__ __launch_bounds__(256) void layernorm_kernel(
    const float* __restrict__ x, const float* __restrict__ gamma,
    const float* __restrict__ beta, __half* __restrict__ out)
{
    const size_t row = (size_t)blockIdx.x * CC;
    const int c = threadIdx.x * 4;
    float4 v = *(const float4*)(x + row + c);

    float s = v.x + v.y + v.z + v.w;
    s = blockReduceSum256(s);
    float mu = s * (1.0f / CC);

    float dx = v.x - mu, dy = v.y - mu, dz = v.z - mu, dw = v.w - mu;
    float ss = dx*dx + dy*dy + dz*dz + dw*dw;
    ss = blockReduceSum256(ss);
    float rstd = rsqrtf(ss * (1.0f / CC) + 1e-6f);

    float4 g = *(const float4*)(gamma + c);
    float4 b = *(const float4*)(beta + c);
    __half2* o = (__half2*)(out + row + c);
    o[0] = __floats2half2_rn(dx * rstd * g.x + b.x, dy * rstd * g.y + b.y);
    o[1] = __floats2half2_rn(dz * rstd * g.z + b.z, dw * rstd * g.w + b.w);
}

// ---------------- fp16 GEMM 128x128x64, cp.async double-buffered, 2 CTA/SM ------
#define GEMM_SMEM (2*128*72*2 + 2*64*136*2)

__global__ __launch_bounds__(256, 2) void h_gemm_kernel(
    const __half* __restrict__ A, const __half* __restrict__ Bm,
    const float* __restrict__ bias, const float* __restrict__ res,
    float* __restrict__ Cf, __half* __restrict__ Ch,
    int N, int K, int do_gelu)
{
    extern __shared__ char gsm[];
    __half (*As)[72]  = (__half(*)[72])gsm;                       // [2*128][72]
    __half (*Bs)[136] = (__half(*)[136])(gsm + 2 * 128 * 72 * 2); // [2*64][136]

    const int tid = threadIdx.x;
    const int lane = tid & 31;
    const int wid = tid >> 5;
    const int bx = blockIdx.x, by = blockIdx.y;
    const int m0w = (wid >> 2) * 64;
    const int n0w = (wid & 3) * 32;
    const int idx = lane & 7;
    const int sel = (lane >> 3) & 3;

    float4 acc[4][4];
    #pragma unroll
    for (int i = 0; i < 4; i++)
        #pragma unroll
        for (int j = 0; j < 4; j++) acc[i][j] = make_float4(0.f, 0.f, 0.f, 0.f);

    auto loadChunk = [&](int k0, int buf) {
        #pragma unroll
        for (int i = 0; i < 4; i++) {
            int c = tid + i * 256;
            int r = c >> 3, c8 = (c & 7) * 8;
            cp16(&As[buf * 128 + r][c8], A + (size_t)(by * 128 + r) * K + k0 + c8);
        }
        #pragma unroll
        for (int i = 0; i < 4; i++) {
            int c = tid + i * 256;
            int r = c >> 4, c8 = (c & 15) * 8;
            cp16(&Bs[buf * 64 + r][c8], Bm + (size_t)(k0 + r) * N + bx * 128 + c8);
        }
        cp_commit();
    };

    const int KT = K >> 6;
    loadChunk(0, 0);
    int buf = 0;
    for (int kt = 0; kt < KT; kt++) {
        if (kt + 1 < KT) { loadChunk((kt + 1) << 6, buf ^ 1); cp_wait1(); }
        else cp_wait0();
        __syncthreads();

        #pragma unroll
        for (int kk = 0; kk < 64; kk += 16) {
            uint32_t af[4][4];
            #pragma unroll
            for (int im = 0; im < 4; im++)
                ldsm_x4(af[im][0], af[im][1], af[im][2], af[im][3],
                        smem_u32(&As[buf * 128 + m0w + im * 16 + (lane & 15)][kk + ((lane >> 4) << 3)]));
            uint32_t bf[4][2];
            #pragma unroll
            for (int inp = 0; inp < 4; inp += 2)
                ldsm_x4_t(bf[inp][0], bf[inp][1], bf[inp + 1][0], bf[inp + 1][1],
                          smem_u32(&Bs[buf * 64 + kk + (sel & 1) * 8 + idx][n0w + inp * 8 + (sel >> 1) * 8]));
            #pragma unroll
            for (int im = 0; im < 4; im++)
                #pragma unroll
                for (int in = 0; in < 4; in++)
                    mma_f16(acc[im][in], af[im][0], af[im][1], af[im][2], af[im][3],
                            bf[in][0], bf[in][1]);
        }
        __syncthreads();
        buf ^= 1;
    }

    // epilogue
    #pragma unroll
    for (int im = 0; im < 4; im++) {
        #pragma unroll
        for (int in = 0; in < 4; in++) {
            int row = by * 128 + m0w + im * 16 + (lane >> 2);
            int col = bx * 128 + n0w + in * 8 + (lane & 3) * 2;
            #pragma unroll
            for (int half = 0; half < 2; half++) {
                int r = row + half * 8;
                float v0 = half ? acc[im][in].z : acc[im][in].x;
                float v1 = half ? acc[im][in].w : acc[im][in].y;
                if (bias) { v0 += bias[col]; v1 += bias[col + 1]; }
                if (do_gelu) {
                    v0 = 0.5f * v0 * (1.0f + erff(v0 * 0.70710678118654752f));
                    v1 = 0.5f * v1 * (1.0f + erff(v1 * 0.70710678118654752f));
                }
                if (res) {
                    v0 += res[(size_t)r * N + col];
                    v1 += res[(size_t)r * N + col + 1];
                }
                if (Ch) {
                    *(__half2*)(Ch + (size_t)r * N + col) = __floats2half2_rn(v0, v1);
                } else {
                    *(float2*)(Cf + (size_t)r * N + col) = make_float2(v0, v1);
                }
            }
        }
    }
}

// ---------------- fused flash attention: 64-key KV tiles, 2 CTA/SM ----------------
// grid (NN/128, B*H), 256 thr. Q tile 128 rows; KV tiles 64 rows double-buffered.
// V smem col 64 = 1.0 (ones column) -> row sum l accumulates in extra MMA accum.
// smem: Q 128x72 + K 2x64x72 + V 2x64x72 = 55296 B
#define FLASH_SMEM_B ((128*72 + 2*64*72 + 2*64*72) * 2)

__global__ __launch_bounds__(256, 2) void flash_kernel(
    const __half* __restrict__ qkv, __half* __restrict__ y)
{
    extern __shared__ __half fsm[];
    __half (*Qs)[72] = (__half(*)[72])fsm;                        // 128x72
    __half (*Ks)[72] = (__half(*)[72])(fsm + 128 * 72);           // 2 x 64x72
    __half (*Vs)[72] = (__half(*)[72])(fsm + 128 * 72 + 2 * 64 * 72); // 2 x 64x72

    const int bh = blockIdx.y;
    const int b = bh >> 4, h = bh & 15;
    const int n0 = blockIdx.x * 128;
    const int tid = threadIdx.x;
    const int lane = tid & 31;
    const int wid = tid >> 5;
    const int idx = lane & 7;
    const int sel = (lane >> 3) & 3;

    const size_t tok0 = (size_t)b * NN;
    const __half* qb = qkv + h * DD;
    const __half* kb = qkv + CC + h * DD;
    const __half* vb = qkv + 2 * CC + h * DD;

    // Q tile: its own cp.async group (g0)
    #pragma unroll
    for (int i = 0; i < 4; i++) {
        int c = tid + i * 256;
        int r = c >> 3, c8 = (c & 7) * 8;
        cp16(&Qs[r][c8], qb + (tok0 + n0 + r) * (3 * CC) + c8);
    }
    cp_commit();

    auto loadKV = [&](int m0, int buf) {
        #pragma unroll
        for (int i = 0; i < 2; i++) {
            int c = tid + i * 256;          // 512 chunks, 64 rows
            int r = c >> 3, c8 = (c & 7) * 8;
            cp16(&Ks[buf * 64 + r][c8], kb + (tok0 + m0 + r) * (3 * CC) + c8);
        }
        #pragma unroll
        for (int i = 0; i < 2; i++) {
            int c = tid + i * 256;
            int r = c >> 3, c8 = (c & 7) * 8;
            cp16(&Vs[buf * 64 + r][c8], vb + (tok0 + m0 + r) * (3 * CC) + c8);
        }
        cp_commit();
    };

    loadKV(0, 0);   // g1

    // ones column at V col 64, zeros 65-71 (both buffers = 128 rows)
    if (tid < 128) {
        __half* p = &Vs[tid][64];
        p[0] = __float2half(1.0f);
        #pragma unroll
        for (int j = 1; j < 8; j++) p[j] = __float2half(0.0f);
    }

    // hoist Q fragment load: wait g0 only (g1 still in flight)
    cp_wait1();
    __syncthreads();
    uint32_t aq[4][4];
    #pragma unroll
    for (int kd = 0; kd < 4; kd++)
        ldsm_x4(aq[kd][0], aq[kd][1], aq[kd][2], aq[kd][3],
                smem_u32(&Qs[wid * 16 + (lane & 15)][kd * 16 + ((lane >> 4) << 3)]));

    float4 acc_o[8];
    float4 acc_l = make_float4(0.f, 0.f, 0.f, 0.f);
    #pragma unroll
    for (int i = 0; i < 8; i++) acc_o[i] = make_float4(0.f, 0.f, 0.f, 0.f);
    float mrow[2] = {-1e30f, -1e30f};

    int buf = 0;
    const int NTILE = NN / 64;        // 32 KV tiles of 64 keys
    for (int jt = 0; jt < NTILE; jt++) {
        if (jt + 1 < NTILE) { loadKV((jt + 1) * 64, buf ^ 1); cp_wait1(); }
        else cp_wait0();
        __syncthreads();

        // S = Q @ K^T  (16 rows x 64 cols per warp)
        float4 acc_s[8];
        #pragma unroll
        for (int i = 0; i < 8; i++) acc_s[i] = make_float4(0.f, 0.f, 0.f, 0.f);
        #pragma unroll
        for (int kd = 0; kd < 4; kd++) {
            #pragma unroll
            for (int inp = 0; inp < 8; inp += 2) {
                uint32_t b0, b1, b2, b3;
                ldsm_x4(b0, b1, b2, b3,
                        smem_u32(&Ks[buf * 64 + inp * 8 + (sel >> 1) * 8 + idx][kd * 16 + (sel & 1) * 8]));
                mma_f16(acc_s[inp],     aq[kd][0], aq[kd][1], aq[kd][2], aq[kd][3], b0, b1);
                mma_f16(acc_s[inp + 1], aq[kd][0], aq[kd][1], aq[kd][2], aq[kd][3], b2, b3);
            }
        }

        // row max (fp32)
        float mx0 = -1e30f, mx1 = -1e30f;
        #pragma unroll
        for (int i = 0; i < 8; i++) {
            mx0 = fmaxf(mx0, fmaxf(acc_s[i].x, acc_s[i].y));
            mx1 = fmaxf(mx1, fmaxf(acc_s[i].z, acc_s[i].w));
        }
        mx0 = fmaxf(mx0, __shfl_xor_sync(0xffffffffu, mx0, 1));
        mx0 = fmaxf(mx0, __shfl_xor_sync(0xffffffffu, mx0, 2));
        mx1 = fmaxf(mx1, __shfl_xor_sync(0xffffffffu, mx1, 1));
        mx1 = fmaxf(mx1, __shfl_xor_sync(0xffffffffu, mx1, 2));
        float mn0 = fmaxf(mrow[0], mx0), mn1 = fmaxf(mrow[1], mx1);
        float al0 = exp2f((mrow[0] - mn0) * L2E), al1 = exp2f((mrow[1] - mn1) * L2E);
        mrow[0] = mn0; mrow[1] = mn1;
        const float nm0 = -mn0 * L2E, nm1 = -mn1 * L2E;

        // rescale O and l
        #pragma unroll
        for (int i = 0; i < 8; i++) {
            acc_o[i].x *= al0; acc_o[i].y *= al0;
            acc_o[i].z *= al1; acc_o[i].w *= al1;
        }
        acc_l.x *= al0; acc_l.y *= al0; acc_l.z *= al1; acc_l.w *= al1;

        // P in fp16 via ex2.approx.f16x2, then O += P @ V (V col 64 = ones -> l)
        #pragma unroll
        for (int ks = 0; ks < 4; ks++) {
            uint32_t a0 = ex2h2(pkh2(fmaf(acc_s[2 * ks].x, L2E, nm0),
                                     fmaf(acc_s[2 * ks].y, L2E, nm0)));
            uint32_t a1 = ex2h2(pkh2(fmaf(acc_s[2 * ks].z, L2E, nm1),
                                     fmaf(acc_s[2 * ks].w, L2E, nm1)));
            uint32_t a2 = ex2h2(pkh2(fmaf(acc_s[2 * ks + 1].x, L2E, nm0),
                                     fmaf(acc_s[2 * ks + 1].y, L2E, nm0)));
            uint32_t a3 = ex2h2(pkh2(fmaf(acc_s[2 * ks + 1].z, L2E, nm1),
                                     fmaf(acc_s[2 * ks + 1].w, L2E, nm1)));
            #pragma unroll
            for (int dp = 0; dp < 4; dp++) {
                uint32_t b0, b1, b2, b3;
                ldsm_x4_t(b0, b1, b2, b3,
                          smem_u32(&Vs[buf * 64 + ks * 16 + (sel & 1) * 8 + idx][dp * 16 + (sel >> 1) * 8]));
                mma_f16(acc_o[2 * dp],     a0, a1, a2, a3, b0, b1);
                mma_f16(acc_o[2 * dp + 1], a0, a1, a2, a3, b2, b3);
            }
            {
                uint32_t b0, b1;
                ldsm_x2_t(b0, b1,
                          smem_u32(&Vs[buf * 64 + ks * 16 + ((lane >> 3) & 1) * 8 + idx][64]));
                mma_f16(acc_l, a0, a1, a2, a3, b0, b1);
            }
        }
        __syncthreads();
        buf ^= 1;
    }

    // l lives in acc_l.x (rows r0) / acc_l.z (rows r0+8) of quad-leader lanes
    float l0 = __shfl_sync(0xffffffffu, acc_l.x, lane & 0x1C);
    float l1 = __shfl_sync(0xffffffffu, acc_l.z, lane & 0x1C);
    float inv0 = 1.0f / l0, inv1 = 1.0f / l1;

    const int r0 = lane >> 2;
    #pragma unroll
    for (int df = 0; df < 8; df++) {
        int col = h * DD + df * 8 + (lane & 3) * 2;
        int n = n0 + wid * 16 + r0;
        *(__half2*)(y + (tok0 + n) * CC + col) =
            __floats2half2_rn(acc_o[df].x * inv0, acc_o[df].y * inv0);
        *(__half2*)(y + (tok0 + n + 8) * CC + col) =
            __floats2half2_rn(acc_o[df].z * inv1, acc_o[df].w * inv1);
    }
}

// ---------------- launch ----------------
extern "C" void kernel_launch(void* const* d_in, const int* in_sizes, int n_in,
                              void* d_out, int out_size)
{
    const float* x      = (const float*)d_in[0];
    const float* Wq     = (const float*)d_in[1];
    const float* Wk     = (const float*)d_in[2];
    const float* Wv     = (const float*)d_in[3];
    const float* Wp     = (const float*)d_in[4];
    const float* bp     = (const float*)d_in[5];
    const float* W1     = (const float*)d_in[6];
    const float* b1     = (const float*)d_in[7];
    const float* W2     = (const float*)d_in[8];
    const float* b2     = (const float*)d_in[9];
    const float* gamma1 = (const float*)d_in[10];
    const float* beta1  = (const float*)d_in[11];
    const float* gamma2 = (const float*)d_in[12];
    const float* beta2  = (const float*)d_in[13];
    float* out = (float*)d_out;

    __half *xn, *qkv, *y, *xn2, *hb, *wqkv, *wp, *w1, *w2;
    float *x1;
    cudaGetSymbolAddress((void**)&xn,   g_xn);
    cudaGetSymbolAddress((void**)&qkv,  g_qkv);
    cudaGetSymbolAddress((void**)&y,    g_y);
    cudaGetSymbolAddress((void**)&x1,   g_x1);
    cudaGetSymbolAddress((void**)&xn2,  g_xn2);
    cudaGetSymbolAddress((void**)&hb,   g_h);
    cudaGetSymbolAddress((void**)&wqkv, g_wqkv);
    cudaGetSymbolAddress((void**)&wp,   g_wp);
    cudaGetSymbolAddress((void**)&w1,   g_w1);
    cudaGetSymbolAddress((void**)&w2,   g_w2);

    cudaFuncSetAttribute(flash_kernel, cudaFuncAttributeMaxDynamicSharedMemorySize, FLASH_SMEM_B);
    cudaFuncSetAttribute(h_gemm_kernel, cudaFuncAttributeMaxDynamicSharedMemorySize, GEMM_SMEM);

    // 0) all weight conversions in ONE launch (qscale folded into Wq)
    conv_all_kernel<<<12288, 256>>>(Wq, Wk, Wv, Wp, W1, W2, wqkv, wp, w1, w2);

    // 1) LN1 -> fp16
    layernorm_kernel<<<TT, 256>>>(x, gamma1, beta1, xn);

    // 2) fused QKV projection: [T,C] @ [C,3C]
    {
        dim3 g(3 * CC / 128, TT / 128);
        h_gemm_kernel<<<g, 256, GEMM_SMEM>>>(xn, wqkv, nullptr, nullptr, nullptr, qkv,
                                             3 * CC, CC, 0);
    }

    // 3) fused flash attention
    {
        dim3 g(NN / 128, BB * HH);
        flash_kernel<<<g, 256, FLASH_SMEM_B>>>(qkv, y);
    }

    // 4) output projection + residual: x1 = x + y@Wp + bp (fp32 out)
    {
        dim3 g(CC / 128, TT / 128);
        h_gemm_kernel<<<g, 256, GEMM_SMEM>>>(y, wp, bp, x, x1, nullptr, CC, CC, 0);
    }

    // 5) LN2 -> fp16
    layernorm_kernel<<<TT, 256>>>(x1, gamma2, beta2, xn2);

    // 6) MLP
    {
        dim3 g(FF / 128, TT / 128);
        h_gemm_kernel<<<g, 256, GEMM_SMEM>>>(xn2, w1, b1, nullptr, nullptr, hb, FF, CC, 1);
    }
    {
        dim3 g(CC / 128, TT / 128);
        h_gemm_kernel<<<g, 256, GEMM_SMEM>>>(hb, w2, b2, x1, out, nullptr, CC, FF, 0);
    }
}